// round 6
// baseline (speedup 1.0000x reference)
#include <cuda_runtime.h>
#include <cstdint>
#include <math.h>

#define NB 8
#define NT 2048
#define NC 512
#define SCALE 0.04419417382415922f   // 1/sqrt(512)

// ---------------- scratch (__device__ globals; allocation-free rule) --------
__device__ __align__(256) uint16_t g_xh [NB * NT * NC];
__device__ __align__(256) uint16_t g_xl [NB * NT * NC];
__device__ __align__(256) uint16_t g_wTh[3 * NC * NC];
__device__ __align__(256) uint16_t g_wTl[3 * NC * NC];
__device__ __align__(256) uint16_t g_qh [NB * NT * NC];
__device__ __align__(256) uint16_t g_ql [NB * NT * NC];
__device__ __align__(256) uint16_t g_kh [NB * NT * NC];
__device__ __align__(256) uint16_t g_kl [NB * NT * NC];
__device__ __align__(256) uint16_t g_vTh[NB * NT * NC];   // [b][c][t]
__device__ __align__(256) uint16_t g_vTl[NB * NT * NC];
__device__ __align__(256) uint16_t g_Ph [(size_t)NB * NT * NT]; // P' [b][t][s]
__device__ __align__(256) uint16_t g_Pl [(size_t)NB * NT * NT];
__device__ __align__(256) float    g_v  [NB * NT * NC];   // fp32 v [b][t][c]
__device__ __align__(256) float    g_lg [(size_t)NB * NT * NT]; // lgT [b][s][t]
__device__ float g_mx [NB * NT];
__device__ float g_inv[NB * NT];

// ---------------- helpers ---------------------------------------------------
__device__ __forceinline__ uint32_t smem_u32(const void* p) {
    uint32_t a;
    asm("{ .reg .u64 t; cvta.to.shared.u64 t, %1; cvt.u32.u64 %0, t; }" : "=r"(a) : "l"(p));
    return a;
}
__device__ __forceinline__ uint32_t cvt2bf(float hi_, float lo_) {
    uint32_t r;
    asm("cvt.rn.satfinite.bf16x2.f32 %0, %1, %2;" : "=r"(r) : "f"(hi_), "f"(lo_));
    return r;
}
__device__ __forceinline__ uint16_t bf16of(float x) { return (uint16_t)cvt2bf(0.f, x); }
__device__ __forceinline__ float fofbf(uint16_t h) { return __uint_as_float((uint32_t)h << 16); }

__device__ __forceinline__ void mma_bf16(float* c, const uint32_t* a, const uint32_t* b) {
    asm volatile(
        "mma.sync.aligned.m16n8k16.row.col.f32.bf16.bf16.f32 "
        "{%0,%1,%2,%3}, {%4,%5,%6,%7}, {%8,%9}, {%0,%1,%2,%3};"
        : "+f"(c[0]), "+f"(c[1]), "+f"(c[2]), "+f"(c[3])
        : "r"(a[0]), "r"(a[1]), "r"(a[2]), "r"(a[3]), "r"(b[0]), "r"(b[1]));
}
__device__ __forceinline__ void cp16(uint32_t dst, const void* src) {
    asm volatile("cp.async.cg.shared.global [%0], [%1], 16;" :: "r"(dst), "l"(src));
}
#define CP_COMMIT() asm volatile("cp.async.commit_group;" ::: "memory")
#define CP_WAIT3()  asm volatile("cp.async.wait_group 3;" ::: "memory")

__device__ __forceinline__ void split2(uint16_t* ch, uint16_t* cl, float a, float b) {
    const uint32_t h = cvt2bf(b, a);
    const float ha = __uint_as_float(h << 16);
    const float hb = __uint_as_float(h & 0xffff0000u);
    const uint32_t l = cvt2bf(b - hb, a - ha);
    *(uint32_t*)ch = h;
    *(uint32_t*)cl = l;
}

// ---------------------------------------------------------------------------
// bf16 split-precision GEMM via mma.sync (HMMA), 4-stage cp.async(16B) pipeline.
//   D[m][n] = sum_k (Ah+Al)[m][k] * (Bh+Bl)[n][k]   (3 MMA terms)
// CTA tile 128x128, BK=32, 256 threads, warp tile 64x32.
// Stage (32KB): A block 16KB (128 rows x [Ah 64B | Al 64B]) + B block 16KB.
// Row layout: chunk c (16B, 0..7) stored at row*128 + ((c ^ (row&7))<<4).
// CSKIP: skip tile if n0+127 < m0.  CKLIM: kend = m0+128.
// EPI16: write C as hi/lo bf16 pair arrays (with optional bias) else fp32.
// ---------------------------------------------------------------------------
template<bool BIAS, bool CSKIP, bool CKLIM, bool EPI16>
__global__ __launch_bounds__(256, 1)
void gemm_bf(const uint16_t* __restrict__ Ahg, const uint16_t* __restrict__ Alg,
             const uint16_t* __restrict__ Bhg, const uint16_t* __restrict__ Blg,
             const float* __restrict__ bias, float* __restrict__ Cg,
             uint16_t* __restrict__ Chg, uint16_t* __restrict__ Clg,
             int lda, int ldb, int ldc, int Ktot,
             size_t sA, size_t sB, size_t sC)
{
    extern __shared__ char smem[];
    const int m0 = blockIdx.y * 128;
    const int n0 = blockIdx.x * 128;
    if (CSKIP && (n0 + 127) < m0) return;

    const uint16_t* Ah = Ahg + (size_t)blockIdx.z * sA;
    const uint16_t* Al = Alg + (size_t)blockIdx.z * sA;
    const uint16_t* Bh = Bhg + (size_t)blockIdx.z * sB;
    const uint16_t* Bl = Blg + (size_t)blockIdx.z * sB;

    const int tid = threadIdx.x;
    const int lane = tid & 31;
    const int wid = tid >> 5;
    const int warp_m = (wid & 1) * 64;
    const int warp_n = (wid >> 1) * 32;
    const int g  = lane >> 2;
    const int tg = lane & 3;
    const uint32_t smem_u = smem_u32(smem);

    // fragment column offsets within a 128B row (chunk-XOR swizzle folded in)
    // word w = w0 + 2j -> chunk j, half w0
    uint32_t colH[4], colL[4];
    {
        const uint32_t w0 = (uint32_t)(tg >> 1) * 8, sub4 = (uint32_t)(tg & 1) * 4;
#pragma unroll
        for (int j = 0; j < 4; j++) {
            colH[j] = (((uint32_t)(j ^ g)) << 4) + w0 + sub4;
            colL[j] = colH[j] ^ 64u;
        }
    }
    uint32_t aoff0[4], aoff1[4], boff[4];
#pragma unroll
    for (int mt = 0; mt < 4; mt++) {
        aoff0[mt] = (uint32_t)(warp_m + mt * 16 + g) * 128;
        aoff1[mt] = aoff0[mt] + 8 * 128;
    }
#pragma unroll
    for (int nt = 0; nt < 4; nt++)
        boff[nt] = 16384u + (uint32_t)(warp_n + nt * 8 + g) * 128;

    // loader: lc = chunk 0..7 (0-3 from H array, 4-7 from L), lr = row base
    const int lc = tid & 7;
    const int lr = tid >> 3;
    const uint16_t* Asrc = (lc < 4) ? Ah : Al;
    const uint16_t* Bsrc = (lc < 4) ? Bh : Bl;
    const int kc = (lc & 3) * 8;   // halfword offset within BK=32 segment

    float acc[4][4][4];
#pragma unroll
    for (int mt = 0; mt < 4; mt++)
#pragma unroll
        for (int nt = 0; nt < 4; nt++)
#pragma unroll
            for (int r = 0; r < 4; r++) acc[mt][nt][r] = 0.f;

    const int kend = CKLIM ? min(Ktot, m0 + 128) : Ktot;
    const int nch = kend >> 5;   // always >= 4 for this problem

    auto load_stage = [&](int slot, int chunk) {
        const uint32_t sbase = smem_u + (uint32_t)slot * 32768u;
        const int k0 = (chunk << 5) + kc;
#pragma unroll
        for (int i = 0; i < 4; i++) {
            const int r = lr + i * 32;
            const uint32_t dst = sbase + (uint32_t)r * 128 + ((uint32_t)(lc ^ (r & 7)) << 4);
            cp16(dst,          Asrc + (size_t)(m0 + r) * lda + k0);
            cp16(dst + 16384u, Bsrc + (size_t)(n0 + r) * ldb + k0);
        }
    };

    // prologue: 3 stages
#pragma unroll
    for (int i = 0; i < 3; i++) {
        load_stage(i, i);
        CP_COMMIT();
    }

    for (int c = 0; c < nch; c++) {
        if (c + 3 < nch) load_stage((c + 3) & 3, c + 3);
        CP_COMMIT();                 // one group per iteration (possibly empty)
        CP_WAIT3();                  // committed = c+4  ==> groups 0..c complete
        __syncthreads();

        const char* base = smem + (size_t)(c & 3) * 32768;
#pragma unroll
        for (int ks = 0; ks < 2; ks++) {
            const uint32_t cH0 = colH[2 * ks],     cH1 = colH[2 * ks + 1];
            const uint32_t cL0 = colL[2 * ks],     cL1 = colL[2 * ks + 1];
            uint32_t ah[4][4], al[4][4], bh[4][2], bl[4][2];
#pragma unroll
            for (int mt = 0; mt < 4; mt++) {
                ah[mt][0] = *(const uint32_t*)(base + aoff0[mt] + cH0);
                ah[mt][1] = *(const uint32_t*)(base + aoff1[mt] + cH0);
                ah[mt][2] = *(const uint32_t*)(base + aoff0[mt] + cH1);
                ah[mt][3] = *(const uint32_t*)(base + aoff1[mt] + cH1);
                al[mt][0] = *(const uint32_t*)(base + aoff0[mt] + cL0);
                al[mt][1] = *(const uint32_t*)(base + aoff1[mt] + cL0);
                al[mt][2] = *(const uint32_t*)(base + aoff0[mt] + cL1);
                al[mt][3] = *(const uint32_t*)(base + aoff1[mt] + cL1);
            }
#pragma unroll
            for (int nt = 0; nt < 4; nt++) {
                bh[nt][0] = *(const uint32_t*)(base + boff[nt] + cH0);
                bh[nt][1] = *(const uint32_t*)(base + boff[nt] + cH1);
                bl[nt][0] = *(const uint32_t*)(base + boff[nt] + cL0);
                bl[nt][1] = *(const uint32_t*)(base + boff[nt] + cL1);
            }
#pragma unroll
            for (int mt = 0; mt < 4; mt++)
#pragma unroll
                for (int nt = 0; nt < 4; nt++) {
                    mma_bf16(acc[mt][nt], ah[mt], bh[nt]);
                    mma_bf16(acc[mt][nt], ah[mt], bl[nt]);
                    mma_bf16(acc[mt][nt], al[mt], bh[nt]);
                }
        }
        __syncthreads();
    }

    // ---- epilogue ----
#pragma unroll
    for (int mt = 0; mt < 4; mt++) {
        const int m = m0 + warp_m + mt * 16 + g;
#pragma unroll
        for (int nt = 0; nt < 4; nt++) {
            const int n = n0 + warp_n + nt * 8 + tg * 2;
            float v00 = acc[mt][nt][0], v01 = acc[mt][nt][1];
            float v10 = acc[mt][nt][2], v11 = acc[mt][nt][3];
            if (BIAS) {
                const float b0 = bias[n], b1 = bias[n + 1];
                v00 += b0; v01 += b1;
                v10 += b0; v11 += b1;
            }
            if (EPI16) {
                uint16_t* ch = Chg + (size_t)blockIdx.z * sC + (size_t)m * ldc + n;
                uint16_t* cl = Clg + (size_t)blockIdx.z * sC + (size_t)m * ldc + n;
                split2(ch, cl, v00, v01);
                split2(ch + (size_t)8 * ldc, cl + (size_t)8 * ldc, v10, v11);
            } else {
                float* crow = Cg + (size_t)blockIdx.z * sC + (size_t)m * ldc + n;
                *(float2*)crow = make_float2(v00, v01);
                *(float2*)(crow + (size_t)8 * ldc) = make_float2(v10, v11);
            }
        }
    }
}

// ---------------------------------------------------------------------------
// x -> bf16 hi/lo, fused with out[..., 0:512] = x
// ---------------------------------------------------------------------------
__global__ void cvt_x(const float4* __restrict__ in, uint2* __restrict__ h4,
                      uint2* __restrict__ l4, float4* __restrict__ out4, int n4)
{
    const int i = blockIdx.x * blockDim.x + threadIdx.x;
    if (i >= n4) return;
    const float4 v = in[i];
    const uint32_t h01 = cvt2bf(v.y, v.x);
    const uint32_t h23 = cvt2bf(v.w, v.z);
    const float hx = __uint_as_float(h01 << 16);
    const float hy = __uint_as_float(h01 & 0xffff0000u);
    const float hz = __uint_as_float(h23 << 16);
    const float hw = __uint_as_float(h23 & 0xffff0000u);
    h4[i] = make_uint2(h01, h23);
    l4[i] = make_uint2(cvt2bf(v.y - hy, v.x - hx), cvt2bf(v.w - hw, v.z - hz));
    const size_t row = (size_t)i >> 7;
    const size_t col = (size_t)i & 127;
    out4[row * 256 + col] = v;
}

// 512x512 transpose + split: WT[n][k] = W[k][n] as bf16 hi/lo
__global__ void trans512cv(const float* __restrict__ W,
                           uint16_t* __restrict__ WTh, uint16_t* __restrict__ WTl)
{
    __shared__ float tile[32][33];
    const int tx = threadIdx.x & 31, ty = threadIdx.x >> 5;
    const int c0 = blockIdx.x * 32, r0 = blockIdx.y * 32;
#pragma unroll
    for (int r = 0; r < 4; r++)
        tile[ty + r * 8][tx] = W[(size_t)(r0 + ty + r * 8) * NC + c0 + tx];
    __syncthreads();
#pragma unroll
    for (int r = 0; r < 4; r++) {
        const float v = tile[tx][ty + r * 8];
        const uint16_t h = bf16of(v);
        const uint16_t l = bf16of(v - fofbf(h));
        const size_t o = (size_t)(c0 + ty + r * 8) * NC + r0 + tx;
        WTh[o] = h;
        WTl[o] = l;
    }
}

// v[b][t][c] fp32 -> vT[b][c][t] bf16 hi/lo
__global__ void trans_btc_cv(const float* __restrict__ in,
                             uint16_t* __restrict__ oh, uint16_t* __restrict__ ol)
{
    __shared__ float tile[32][33];
    const int c0 = blockIdx.x * 32, t0 = blockIdx.y * 32, b = blockIdx.z;
    const float* ip = in + (size_t)b * NT * NC;
    const int tx = threadIdx.x & 31, ty = threadIdx.x >> 5;
#pragma unroll
    for (int r = 0; r < 4; r++)
        tile[ty + r * 8][tx] = ip[(size_t)(t0 + ty + r * 8) * NC + c0 + tx];
    __syncthreads();
#pragma unroll
    for (int r = 0; r < 4; r++) {
        const float v = tile[tx][ty + r * 8];
        const uint16_t h = bf16of(v);
        const uint16_t l = bf16of(v - fofbf(h));
        const size_t o = (size_t)b * NT * NC + (size_t)(c0 + ty + r * 8) * NT + t0 + tx;
        oh[o] = h;
        ol[o] = l;
    }
}

// ---------------------------------------------------------------------------
// softmax pass 1: per key-column s, reduce over t >= s -> mx[s], 1/sum
// ---------------------------------------------------------------------------
__global__ void softmax_p1(const float* __restrict__ lg,
                           float* __restrict__ mx, float* __restrict__ inv)
{
    const int s = blockIdx.x, b = blockIdx.y;
    const float* row = lg + ((size_t)b * NT + s) * NT;
    __shared__ float red[256];
    const int tid = threadIdx.x;

    float lmax = -3.4e38f;
    for (int t = s + tid; t < NT; t += 256) lmax = fmaxf(lmax, row[t]);
    red[tid] = lmax;
    __syncthreads();
    for (int off = 128; off > 0; off >>= 1) {
        if (tid < off) red[tid] = fmaxf(red[tid], red[tid + off]);
        __syncthreads();
    }
    const float m = red[0] * SCALE;
    __syncthreads();

    float lsum = 0.f;
    for (int t = s + tid; t < NT; t += 256) lsum += __expf(row[t] * SCALE - m);
    red[tid] = lsum;
    __syncthreads();
    for (int off = 128; off > 0; off >>= 1) {
        if (tid < off) red[tid] += red[tid + off];
        __syncthreads();
    }
    if (tid == 0) {
        mx[b * NT + s]  = m;
        inv[b * NT + s] = 1.f / red[0];
    }
}

// ---------------------------------------------------------------------------
// softmax pass 2: exp + normalize + transpose -> P'[b][t][s] bf16 hi/lo
// ---------------------------------------------------------------------------
__global__ void softmax_p2(const float* __restrict__ lg, const float* __restrict__ mx,
                           const float* __restrict__ inv,
                           uint16_t* __restrict__ Ph, uint16_t* __restrict__ Pl)
{
    const int ti = blockIdx.x, si = blockIdx.y, b = blockIdx.z;
    if (si * 32 >= ti * 32 + 128) return;   // never read by the read-GEMM
    __shared__ float tile[32][33];
    const int tx = threadIdx.x & 31, ty = threadIdx.x >> 5;
    const int t = ti * 32 + tx;
#pragma unroll
    for (int r = 0; r < 4; r++) {
        const int s = si * 32 + ty + r * 8;
        float p = 0.f;
        if (t >= s) {
            const float val = lg[((size_t)b * NT + s) * NT + t];
            p = __expf(val * SCALE - mx[b * NT + s]) * inv[b * NT + s];
        }
        tile[ty + r * 8][tx] = p;
    }
    __syncthreads();
    const int s2 = si * 32 + tx;
#pragma unroll
    for (int r = 0; r < 4; r++) {
        const int t2 = ti * 32 + ty + r * 8;
        const float v = tile[tx][ty + r * 8];
        const uint16_t h = bf16of(v);
        const uint16_t l = bf16of(v - fofbf(h));
        const size_t o = ((size_t)b * NT + t2) * NT + s2;
        Ph[o] = h;
        Pl[o] = l;
    }
}

// ---------------------------------------------------------------------------
extern "C" void kernel_launch(void* const* d_in, const int* in_sizes, int n_in,
                              void* d_out, int out_size)
{
    const float* x  = (const float*)d_in[0];
    const float* Wq = (const float*)d_in[1];
    const float* bq = (const float*)d_in[2];
    const float* Wk = (const float*)d_in[3];
    const float* bk = (const float*)d_in[4];
    const float* Wv = (const float*)d_in[5];
    const float* bv = (const float*)d_in[6];
    float* out = (float*)d_out;

    uint16_t *xh, *xl, *wTh, *wTl, *qh, *ql, *kh, *kl, *vTh, *vTl, *Ph, *Pl;
    float *v, *lg, *mx, *inv;
    cudaGetSymbolAddress((void**)&xh,  g_xh);
    cudaGetSymbolAddress((void**)&xl,  g_xl);
    cudaGetSymbolAddress((void**)&wTh, g_wTh);
    cudaGetSymbolAddress((void**)&wTl, g_wTl);
    cudaGetSymbolAddress((void**)&qh,  g_qh);
    cudaGetSymbolAddress((void**)&ql,  g_ql);
    cudaGetSymbolAddress((void**)&kh,  g_kh);
    cudaGetSymbolAddress((void**)&kl,  g_kl);
    cudaGetSymbolAddress((void**)&vTh, g_vTh);
    cudaGetSymbolAddress((void**)&vTl, g_vTl);
    cudaGetSymbolAddress((void**)&Ph,  g_Ph);
    cudaGetSymbolAddress((void**)&Pl,  g_Pl);
    cudaGetSymbolAddress((void**)&v,   g_v);
    cudaGetSymbolAddress((void**)&lg,  g_lg);
    cudaGetSymbolAddress((void**)&mx,  g_mx);
    cudaGetSymbolAddress((void**)&inv, g_inv);

    const int SMEM = 4 * 32768;   // 131072
    cudaFuncSetAttribute(gemm_bf<true,  false, false, true >, cudaFuncAttributeMaxDynamicSharedMemorySize, SMEM);
    cudaFuncSetAttribute(gemm_bf<true,  false, false, false>, cudaFuncAttributeMaxDynamicSharedMemorySize, SMEM);
    cudaFuncSetAttribute(gemm_bf<false, true,  false, false>, cudaFuncAttributeMaxDynamicSharedMemorySize, SMEM);
    cudaFuncSetAttribute(gemm_bf<false, false, true,  false>, cudaFuncAttributeMaxDynamicSharedMemorySize, SMEM);

    const size_t strBT  = (size_t)NT * NC;
    const size_t strLG  = (size_t)NT * NT;
    const size_t strOUT = (size_t)NT * (2 * NC);

    // 0) operand prep: x -> bf16 h/l (+ copy x to out); W -> transposed bf16 h/l
    cvt_x<<<(NB * NT * NC / 4 + 255) / 256, 256>>>(
        (const float4*)x, (uint2*)xh, (uint2*)xl, (float4*)out, NB * NT * NC / 4);
    trans512cv<<<dim3(16, 16), 256>>>(Wq, wTh + 0 * NC * NC, wTl + 0 * NC * NC);
    trans512cv<<<dim3(16, 16), 256>>>(Wk, wTh + 1 * NC * NC, wTl + 1 * NC * NC);
    trans512cv<<<dim3(16, 16), 256>>>(Wv, wTh + 2 * NC * NC, wTl + 2 * NC * NC);

    // 1) QKV projections (M=16384, N=512, K=512). Q,K epilogue -> bf16 h/l.
    {
        dim3 grid(NC / 128, (NB * NT) / 128, 1);
        gemm_bf<true, false, false, true><<<grid, 256, SMEM>>>(
            xh, xl, wTh + 0 * NC * NC, wTl + 0 * NC * NC, bq,
            nullptr, qh, ql, NC, NC, NC, NC, 0, 0, 0);
        gemm_bf<true, false, false, true><<<grid, 256, SMEM>>>(
            xh, xl, wTh + 1 * NC * NC, wTl + 1 * NC * NC, bk,
            nullptr, kh, kl, NC, NC, NC, NC, 0, 0, 0);
        gemm_bf<true, false, false, false><<<grid, 256, SMEM>>>(
            xh, xl, wTh + 2 * NC * NC, wTl + 2 * NC * NC, bv,
            v, nullptr, nullptr, NC, NC, NC, NC, 0, 0, 0);
    }

    // 1b) v -> vT [b][c][t] bf16 h/l
    trans_btc_cv<<<dim3(NC / 32, NT / 32, NB), 256>>>(v, vTh, vTl);

    // 2) logitsT[b][s][t] = sum_c k[b,s,c] * q[b,t,c]  (causal tile skip)
    {
        dim3 grid(NT / 128, NT / 128, NB);
        gemm_bf<false, true, false, false><<<grid, 256, SMEM>>>(
            kh, kl, qh, ql, nullptr, lg, nullptr, nullptr,
            NC, NC, NT, NC, strBT, strBT, strLG);
    }

    // 3) softmax over t (column softmax) -> P'[b][t][s] bf16 h/l
    softmax_p1<<<dim3(NT, NB), 256>>>(lg, mx, inv);
    softmax_p2<<<dim3(NT / 32, NT / 32, NB), 256>>>(lg, mx, inv, Ph, Pl);

    // 4) read[b][t][v] = sum_s P'[b,t,s] * vT[b,v,s]  -> out[..., 512:1024]
    {
        dim3 grid(NC / 128, NT / 128, NB);
        gemm_bf<false, false, true, false><<<grid, 256, SMEM>>>(
            Ph, Pl, vTh, vTl, nullptr, out + NC, nullptr, nullptr,
            NT, NT, 2 * NC, NT, strLG, (size_t)NC * NT, strOUT);
    }
}

// round 7
// speedup vs baseline: 1.7512x; 1.7512x over previous
#include <cuda_runtime.h>
#include <cstdint>
#include <math.h>

#define NB 8
#define NT 2048
#define NC 512
#define SCALE 0.04419417382415922f   // 1/sqrt(512)

// ---------------- scratch (__device__ globals; allocation-free rule) --------
__device__ __align__(256) float g_xr [NB * NT * NC];          // x, tf32-rounded
__device__ __align__(256) float g_wT [3 * NC * NC];           // W^T, tf32-rounded
__device__ __align__(256) float g_q  [NB * NT * NC];          // tf32-rounded
__device__ __align__(256) float g_k  [NB * NT * NC];          // tf32-rounded
__device__ __align__(256) float g_v  [NB * NT * NC];          // fp32 [b][t][c]
__device__ __align__(256) float g_vT [NB * NT * NC];          // tf32-rounded [b][c][t]
__device__ __align__(256) float g_lg [(size_t)NB * NT * NT];  // logitsT [b][s][t] fp32
__device__ __align__(256) float g_p  [(size_t)NB * NT * NT];  // P' [b][t][s] tf32-rounded
__device__ float g_mx [NB * NT];
__device__ float g_inv[NB * NT];

// ---------------- helpers ---------------------------------------------------
__device__ __forceinline__ float tf32r(float x) {
    float r;
    asm("cvt.rna.tf32.f32 %0, %1;" : "=f"(r) : "f"(x));
    return r;
}
__device__ __forceinline__ void mma_tf32(float* c, const uint32_t* a, const uint32_t* b) {
    asm volatile(
        "mma.sync.aligned.m16n8k8.row.col.f32.tf32.tf32.f32 "
        "{%0,%1,%2,%3}, {%4,%5,%6,%7}, {%8,%9}, {%0,%1,%2,%3};"
        : "+f"(c[0]), "+f"(c[1]), "+f"(c[2]), "+f"(c[3])
        : "r"(a[0]), "r"(a[1]), "r"(a[2]), "r"(a[3]), "r"(b[0]), "r"(b[1]));
}

// ---------------------------------------------------------------------------
// Single-pass tf32 GEMM via mma.sync m16n8k8:
//   D[m][n] = sum_k A[m][k] * B[n][k]   (A,B fp32 pre-rounded to tf32)
// CTA tile 128x128, BK=32, 256 threads, warp tile 64x32, 2-stage smem
// (register-staged global prefetch -> STS, one __syncthreads per chunk).
// Stage (32KB): A 16KB + B 16KB; 128 rows x 128B; 16B chunk c at
//   row*128 + ((c ^ (row&7))<<4).
// CSKIP: skip tile if n0+127 < m0.  CKLIM: kend = m0+128.
// ROUND: round output to tf32 before store (feeds a later GEMM).
// ---------------------------------------------------------------------------
template<bool BIAS, bool CSKIP, bool CKLIM, bool ROUND>
__global__ __launch_bounds__(256, 1)
void gemm_tf(const float* __restrict__ Ag, const float* __restrict__ Bg,
             const float* __restrict__ bias, float* __restrict__ Cg,
             int lda, int ldb, int ldc, int Ktot,
             size_t sA, size_t sB, size_t sC)
{
    extern __shared__ char smem[];
    const int m0 = blockIdx.y * 128;
    const int n0 = blockIdx.x * 128;
    if (CSKIP && (n0 + 127) < m0) return;

    const float* A = Ag + (size_t)blockIdx.z * sA;
    const float* B = Bg + (size_t)blockIdx.z * sB;

    const int tid = threadIdx.x;
    const int lane = tid & 31;
    const int wid = tid >> 5;
    const int warp_m = (wid & 1) * 64;
    const int warp_n = (wid >> 1) * 32;
    const int g  = lane >> 2;    // 0..7
    const int tg = lane & 3;     // 0..3

    // fragment column offsets within a 128B row, per k-step ks (chunks 2ks, 2ks+1)
    uint32_t col0[4], col1[4];
#pragma unroll
    for (int ks = 0; ks < 4; ks++) {
        col0[ks] = (((uint32_t)((2 * ks)     ^ g)) << 4) + (uint32_t)tg * 4;
        col1[ks] = (((uint32_t)((2 * ks + 1) ^ g)) << 4) + (uint32_t)tg * 4;
    }
    uint32_t aoff[4], boff[4];
#pragma unroll
    for (int mt = 0; mt < 4; mt++)
        aoff[mt] = (uint32_t)(warp_m + mt * 16 + g) * 128;
#pragma unroll
    for (int nt = 0; nt < 4; nt++)
        boff[nt] = 16384u + (uint32_t)(warp_n + nt * 8 + g) * 128;

    // loader: lc = 16B chunk 0..7, lr = row base 0..31 (+32i)
    const int lc = tid & 7;
    const int lr = tid >> 3;

    float acc[4][4][4];
#pragma unroll
    for (int mt = 0; mt < 4; mt++)
#pragma unroll
        for (int nt = 0; nt < 4; nt++)
#pragma unroll
            for (int r = 0; r < 4; r++) acc[mt][nt][r] = 0.f;

    const int kend = CKLIM ? min(Ktot, m0 + 128) : Ktot;
    const int nch = kend >> 5;   // >= 4 always here

    float4 pa[4], pb[4];
    auto load_regs = [&](int chunk) {
        const int k0 = (chunk << 5) + lc * 4;
#pragma unroll
        for (int i = 0; i < 4; i++) {
            const int r = lr + i * 32;
            pa[i] = *(const float4*)(A + (size_t)(m0 + r) * lda + k0);
            pb[i] = *(const float4*)(B + (size_t)(n0 + r) * ldb + k0);
        }
    };
    auto store_stage = [&](int slot) {
        char* sbase = smem + (size_t)slot * 32768;
#pragma unroll
        for (int i = 0; i < 4; i++) {
            const int r = lr + i * 32;
            const uint32_t off = (uint32_t)r * 128 + ((uint32_t)(lc ^ (r & 7)) << 4);
            *(float4*)(sbase + off)          = pa[i];
            *(float4*)(sbase + 16384 + off)  = pb[i];
        }
    };

    load_regs(0);
    store_stage(0);
    __syncthreads();

    for (int c = 0; c < nch; c++) {
        if (c + 1 < nch) load_regs(c + 1);

        const char* base = smem + (size_t)(c & 1) * 32768;
#pragma unroll
        for (int ks = 0; ks < 4; ks++) {
            const uint32_t c0 = col0[ks], c1 = col1[ks];
            uint32_t a[4][4], b[4][2];
#pragma unroll
            for (int mt = 0; mt < 4; mt++) {
                a[mt][0] = *(const uint32_t*)(base + aoff[mt] + c0);
                a[mt][1] = *(const uint32_t*)(base + aoff[mt] + 8 * 128 + c0);
                a[mt][2] = *(const uint32_t*)(base + aoff[mt] + c1);
                a[mt][3] = *(const uint32_t*)(base + aoff[mt] + 8 * 128 + c1);
            }
#pragma unroll
            for (int nt = 0; nt < 4; nt++) {
                b[nt][0] = *(const uint32_t*)(base + boff[nt] + c0);
                b[nt][1] = *(const uint32_t*)(base + boff[nt] + c1);
            }
#pragma unroll
            for (int mt = 0; mt < 4; mt++)
#pragma unroll
                for (int nt = 0; nt < 4; nt++)
                    mma_tf32(acc[mt][nt], a[mt], b[nt]);
        }

        if (c + 1 < nch) store_stage((c + 1) & 1);
        __syncthreads();
    }

    // ---- epilogue ----
    float* C = Cg + (size_t)blockIdx.z * sC;
#pragma unroll
    for (int mt = 0; mt < 4; mt++) {
        const int m = m0 + warp_m + mt * 16 + g;
#pragma unroll
        for (int nt = 0; nt < 4; nt++) {
            const int n = n0 + warp_n + nt * 8 + tg * 2;
            float v00 = acc[mt][nt][0], v01 = acc[mt][nt][1];
            float v10 = acc[mt][nt][2], v11 = acc[mt][nt][3];
            if (BIAS) {
                const float b0 = bias[n], b1 = bias[n + 1];
                v00 += b0; v01 += b1;
                v10 += b0; v11 += b1;
            }
            if (ROUND) {
                v00 = tf32r(v00); v01 = tf32r(v01);
                v10 = tf32r(v10); v11 = tf32r(v11);
            }
            float* crow = C + (size_t)m * ldc + n;
            *(float2*)crow = make_float2(v00, v01);
            *(float2*)(crow + (size_t)8 * ldc) = make_float2(v10, v11);
        }
    }
}

// ---------------------------------------------------------------------------
// x -> tf32-rounded copy, fused with out[..., 0:512] = x
// ---------------------------------------------------------------------------
__global__ void cvt_x(const float4* __restrict__ in, float4* __restrict__ xr4,
                      float4* __restrict__ out4, int n4)
{
    const int i = blockIdx.x * blockDim.x + threadIdx.x;
    if (i >= n4) return;
    const float4 v = in[i];
    xr4[i] = make_float4(tf32r(v.x), tf32r(v.y), tf32r(v.z), tf32r(v.w));
    const size_t row = (size_t)i >> 7;
    const size_t col = (size_t)i & 127;
    out4[row * 256 + col] = v;
}

// 512x512 transpose + tf32 round: WT[n][k] = W[k][n]
__global__ void trans512cv(const float* __restrict__ W, float* __restrict__ WT)
{
    __shared__ float tile[32][33];
    const int tx = threadIdx.x & 31, ty = threadIdx.x >> 5;
    const int c0 = blockIdx.x * 32, r0 = blockIdx.y * 32;
#pragma unroll
    for (int r = 0; r < 4; r++)
        tile[ty + r * 8][tx] = W[(size_t)(r0 + ty + r * 8) * NC + c0 + tx];
    __syncthreads();
#pragma unroll
    for (int r = 0; r < 4; r++)
        WT[(size_t)(c0 + ty + r * 8) * NC + r0 + tx] = tf32r(tile[tx][ty + r * 8]);
}

// v[b][t][c] fp32 -> vT[b][c][t] tf32-rounded
__global__ void trans_btc_cv(const float* __restrict__ in, float* __restrict__ outp)
{
    __shared__ float tile[32][33];
    const int c0 = blockIdx.x * 32, t0 = blockIdx.y * 32, b = blockIdx.z;
    const float* ip = in + (size_t)b * NT * NC;
    float* op = outp + (size_t)b * NT * NC;
    const int tx = threadIdx.x & 31, ty = threadIdx.x >> 5;
#pragma unroll
    for (int r = 0; r < 4; r++)
        tile[ty + r * 8][tx] = ip[(size_t)(t0 + ty + r * 8) * NC + c0 + tx];
    __syncthreads();
#pragma unroll
    for (int r = 0; r < 4; r++)
        op[(size_t)(c0 + ty + r * 8) * NT + t0 + tx] = tf32r(tile[tx][ty + r * 8]);
}

// ---------------------------------------------------------------------------
// softmax pass 1: per key-column s, reduce over t >= s -> mx[s], 1/sum
// ---------------------------------------------------------------------------
__global__ void softmax_p1(const float* __restrict__ lg,
                           float* __restrict__ mx, float* __restrict__ inv)
{
    const int s = blockIdx.x, b = blockIdx.y;
    const float* row = lg + ((size_t)b * NT + s) * NT;
    __shared__ float red[256];
    const int tid = threadIdx.x;

    float lmax = -3.4e38f;
    for (int t = s + tid; t < NT; t += 256) lmax = fmaxf(lmax, row[t]);
    red[tid] = lmax;
    __syncthreads();
    for (int off = 128; off > 0; off >>= 1) {
        if (tid < off) red[tid] = fmaxf(red[tid], red[tid + off]);
        __syncthreads();
    }
    const float m = red[0] * SCALE;
    __syncthreads();

    float lsum = 0.f;
    for (int t = s + tid; t < NT; t += 256) lsum += __expf(row[t] * SCALE - m);
    red[tid] = lsum;
    __syncthreads();
    for (int off = 128; off > 0; off >>= 1) {
        if (tid < off) red[tid] += red[tid + off];
        __syncthreads();
    }
    if (tid == 0) {
        mx[b * NT + s]  = m;
        inv[b * NT + s] = 1.f / red[0];
    }
}

// ---------------------------------------------------------------------------
// softmax pass 2: exp + normalize + transpose -> P'[b][t][s] tf32-rounded
// ---------------------------------------------------------------------------
__global__ void softmax_p2(const float* __restrict__ lg, const float* __restrict__ mx,
                           const float* __restrict__ inv, float* __restrict__ P)
{
    const int ti = blockIdx.x, si = blockIdx.y, b = blockIdx.z;
    if (si * 32 >= ti * 32 + 128) return;   // never read by the read-GEMM
    __shared__ float tile[32][33];
    const int tx = threadIdx.x & 31, ty = threadIdx.x >> 5;
    const int t = ti * 32 + tx;
#pragma unroll
    for (int r = 0; r < 4; r++) {
        const int s = si * 32 + ty + r * 8;
        float p = 0.f;
        if (t >= s) {
            const float val = lg[((size_t)b * NT + s) * NT + t];
            p = __expf(val * SCALE - mx[b * NT + s]) * inv[b * NT + s];
        }
        tile[ty + r * 8][tx] = p;
    }
    __syncthreads();
    const int s2 = si * 32 + tx;
#pragma unroll
    for (int r = 0; r < 4; r++) {
        const int t2 = ti * 32 + ty + r * 8;
        P[((size_t)b * NT + t2) * NT + s2] = tf32r(tile[tx][ty + r * 8]);
    }
}

// ---------------------------------------------------------------------------
extern "C" void kernel_launch(void* const* d_in, const int* in_sizes, int n_in,
                              void* d_out, int out_size)
{
    const float* x  = (const float*)d_in[0];
    const float* Wq = (const float*)d_in[1];
    const float* bq = (const float*)d_in[2];
    const float* Wk = (const float*)d_in[3];
    const float* bk = (const float*)d_in[4];
    const float* Wv = (const float*)d_in[5];
    const float* bv = (const float*)d_in[6];
    float* out = (float*)d_out;

    float *xr, *wT, *q, *k, *v, *vT, *lg, *p, *mx, *inv;
    cudaGetSymbolAddress((void**)&xr,  g_xr);
    cudaGetSymbolAddress((void**)&wT,  g_wT);
    cudaGetSymbolAddress((void**)&q,   g_q);
    cudaGetSymbolAddress((void**)&k,   g_k);
    cudaGetSymbolAddress((void**)&v,   g_v);
    cudaGetSymbolAddress((void**)&vT,  g_vT);
    cudaGetSymbolAddress((void**)&lg,  g_lg);
    cudaGetSymbolAddress((void**)&p,   g_p);
    cudaGetSymbolAddress((void**)&mx,  g_mx);
    cudaGetSymbolAddress((void**)&inv, g_inv);

    const int SMEM = 65536;
    cudaFuncSetAttribute(gemm_tf<true,  false, false, true >, cudaFuncAttributeMaxDynamicSharedMemorySize, SMEM);
    cudaFuncSetAttribute(gemm_tf<true,  false, false, false>, cudaFuncAttributeMaxDynamicSharedMemorySize, SMEM);
    cudaFuncSetAttribute(gemm_tf<false, true,  false, false>, cudaFuncAttributeMaxDynamicSharedMemorySize, SMEM);
    cudaFuncSetAttribute(gemm_tf<false, false, true,  false>, cudaFuncAttributeMaxDynamicSharedMemorySize, SMEM);

    const size_t strBT  = (size_t)NT * NC;
    const size_t strLG  = (size_t)NT * NT;
    const size_t strOUT = (size_t)NT * (2 * NC);

    // 0) operand prep: x -> tf32 (+ copy x to out); W -> transposed tf32
    cvt_x<<<(NB * NT * NC / 4 + 255) / 256, 256>>>(
        (const float4*)x, (float4*)xr, (float4*)out, NB * NT * NC / 4);
    trans512cv<<<dim3(16, 16), 256>>>(Wq, wT + 0 * NC * NC);
    trans512cv<<<dim3(16, 16), 256>>>(Wk, wT + 1 * NC * NC);
    trans512cv<<<dim3(16, 16), 256>>>(Wv, wT + 2 * NC * NC);

    // 1) QKV projections (M=16384, N=512, K=512); q,k rounded for next GEMM
    {
        dim3 grid(NC / 128, (NB * NT) / 128, 1);
        gemm_tf<true, false, false, true><<<grid, 256, SMEM>>>(
            xr, wT + 0 * NC * NC, bq, q, NC, NC, NC, NC, 0, 0, 0);
        gemm_tf<true, false, false, true><<<grid, 256, SMEM>>>(
            xr, wT + 1 * NC * NC, bk, k, NC, NC, NC, NC, 0, 0, 0);
        gemm_tf<true, false, false, false><<<grid, 256, SMEM>>>(
            xr, wT + 2 * NC * NC, bv, v, NC, NC, NC, NC, 0, 0, 0);
    }

    // 1b) v -> vT [b][c][t], tf32-rounded
    trans_btc_cv<<<dim3(NC / 32, NT / 32, NB), 256>>>(v, vT);

    // 2) logitsT[b][s][t] = sum_c k[b,s,c] * q[b,t,c]  (causal tile skip)
    {
        dim3 grid(NT / 128, NT / 128, NB);
        gemm_tf<false, true, false, false><<<grid, 256, SMEM>>>(
            k, q, nullptr, lg, NC, NC, NT, NC, strBT, strBT, strLG);
    }

    // 3) softmax over t (column softmax) -> P'[b][t][s] tf32-rounded
    softmax_p1<<<dim3(NT, NB), 256>>>(lg, mx, inv);
    softmax_p2<<<dim3(NT / 32, NT / 32, NB), 256>>>(lg, mx, inv, p);

    // 4) read[b][t][v] = sum_s P'[b,t,s] * vT[b,v,s]  -> out[..., 512:1024]
    {
        dim3 grid(NC / 128, NT / 128, NB);
        gemm_tf<false, false, true, false><<<grid, 256, SMEM>>>(
            p, vT, nullptr, out + NC, NT, NT, 2 * NC, NT,
            strLG, (size_t)NC * NT, strOUT);
    }
}

// round 9
// speedup vs baseline: 1.8544x; 1.0590x over previous
#include <cuda_runtime.h>
#include <cstdint>
#include <math.h>

#define NB 8
#define NT 2048
#define NC 512
#define SCALE 0.04419417382415922f   // 1/sqrt(512)

// ---------------- scratch (__device__ globals; allocation-free rule) --------
__device__ __align__(256) float g_xr [NB * NT * NC];          // x, tf32-rounded
__device__ __align__(256) float g_wT [3 * NC * NC];           // W^T, tf32-rounded
__device__ __align__(256) float g_q  [NB * NT * NC];          // tf32-rounded
__device__ __align__(256) float g_k  [NB * NT * NC];          // tf32-rounded
__device__ __align__(256) float g_vT [NB * NT * NC];          // tf32-rounded [b][c][t]
__device__ __align__(256) float g_lg [(size_t)NB * NT * NT];  // logitsT [b][s][t] fp32
__device__ __align__(256) float g_p  [(size_t)NB * NT * NT];  // P' [b][t][s] tf32-rounded
__device__ float g_mx [NB * NT];
__device__ float g_inv[NB * NT];

// ---------------- helpers ---------------------------------------------------
__device__ __forceinline__ float tf32r(float x) {
    float r;
    asm("cvt.rna.tf32.f32 %0, %1;" : "=f"(r) : "f"(x));
    return r;
}
__device__ __forceinline__ void mma_tf32(float* c, const uint32_t* a, const uint32_t* b) {
    asm volatile(
        "mma.sync.aligned.m16n8k8.row.col.f32.tf32.tf32.f32 "
        "{%0,%1,%2,%3}, {%4,%5,%6,%7}, {%8,%9}, {%0,%1,%2,%3};"
        : "+f"(c[0]), "+f"(c[1]), "+f"(c[2]), "+f"(c[3])
        : "r"(a[0]), "r"(a[1]), "r"(a[2]), "r"(a[3]), "r"(b[0]), "r"(b[1]));
}

// ---------------------------------------------------------------------------
// Single-pass tf32 GEMM via mma.sync m16n8k8:
//   D[m][n] = sum_k A[m][k] * B[n][k]   (A,B fp32 pre-rounded to tf32)
// CTA tile 128x128, BK=64, 256 threads, warp tile 64x32, 2-stage smem
// (register-staged global prefetch -> STS, one __syncthreads per chunk).
// Stage (64KB): A-blk0 | A-blk1 | B-blk0 | B-blk1, each 16KB = 128 rows x
//   32 floats; 16B chunk c of row r at r*128 + ((c ^ (r&7))<<4).
// CSKIP: skip tile if n0+127 < m0.  CKLIM: kend = m0+128.
// ROUND: tf32-round output.  BATCHN: n is a global batched index (b = n>>11),
//   C addressed as Cg + b*sC + m*ldc + (n&2047).  BIASM: bias indexed by m.
// ---------------------------------------------------------------------------
template<bool BIASN, bool BIASM, bool CSKIP, bool CKLIM, bool ROUND, bool BATCHN>
__global__ __launch_bounds__(256, 1)
void gemm_tf(const float* __restrict__ Ag, const float* __restrict__ Bg,
             const float* __restrict__ bias, float* __restrict__ Cg,
             int lda, int ldb, int ldc, int Ktot,
             size_t sA, size_t sB, size_t sC)
{
    extern __shared__ char smem[];
    const int m0 = blockIdx.y * 128;
    const int n0 = blockIdx.x * 128;
    if (CSKIP && (n0 + 127) < m0) return;

    const float* A = Ag + (size_t)blockIdx.z * sA;
    const float* B = Bg + (size_t)blockIdx.z * sB;

    const int tid = threadIdx.x;
    const int lane = tid & 31;
    const int wid = tid >> 5;
    const int warp_m = (wid & 1) * 64;
    const int warp_n = (wid >> 1) * 32;
    const int g  = lane >> 2;    // 0..7
    const int tg = lane & 3;     // 0..3

    // within-block fragment column offsets (chunks 2j, 2j+1 of a 32-float row)
    uint32_t col0[4], col1[4];
#pragma unroll
    for (int j = 0; j < 4; j++) {
        col0[j] = (((uint32_t)((2 * j)     ^ g)) << 4) + (uint32_t)tg * 4;
        col1[j] = (((uint32_t)((2 * j + 1) ^ g)) << 4) + (uint32_t)tg * 4;
    }
    uint32_t aoff[4], boff[4];
#pragma unroll
    for (int mt = 0; mt < 4; mt++)
        aoff[mt] = (uint32_t)(warp_m + mt * 16 + g) * 128;
#pragma unroll
    for (int nt = 0; nt < 4; nt++)
        boff[nt] = (uint32_t)(warp_n + nt * 8 + g) * 128;

    // loader: lc = 16B chunk 0..7 within a 32-float row-block, lr = row base
    const int lc = tid & 7;
    const int lr = tid >> 3;

    float acc[4][4][4];
#pragma unroll
    for (int mt = 0; mt < 4; mt++)
#pragma unroll
        for (int nt = 0; nt < 4; nt++)
#pragma unroll
            for (int r = 0; r < 4; r++) acc[mt][nt][r] = 0.f;

    const int kend = CKLIM ? min(Ktot, m0 + 128) : Ktot;
    const int nch = kend >> 6;   // BK = 64; >= 2 always here

    float4 pa[8], pb[8];
    auto load_regs = [&](int chunk) {
        const int k0 = (chunk << 6) + lc * 4;
#pragma unroll
        for (int i = 0; i < 4; i++) {
            const int r = lr + i * 32;
            const float* ar = A + (size_t)(m0 + r) * lda + k0;
            const float* br = B + (size_t)(n0 + r) * ldb + k0;
            pa[i]     = *(const float4*)ar;
            pa[i + 4] = *(const float4*)(ar + 32);
            pb[i]     = *(const float4*)br;
            pb[i + 4] = *(const float4*)(br + 32);
        }
    };
    auto store_stage = [&](int slot) {
        char* sbase = smem + (size_t)slot * 65536;
#pragma unroll
        for (int i = 0; i < 4; i++) {
            const int r = lr + i * 32;
            const uint32_t off = (uint32_t)r * 128 + ((uint32_t)(lc ^ (r & 7)) << 4);
            *(float4*)(sbase + off)          = pa[i];      // A blk0
            *(float4*)(sbase + 16384 + off)  = pa[i + 4];  // A blk1
            *(float4*)(sbase + 32768 + off)  = pb[i];      // B blk0
            *(float4*)(sbase + 49152 + off)  = pb[i + 4];  // B blk1
        }
    };

    load_regs(0);
    store_stage(0);
    __syncthreads();

    for (int c = 0; c < nch; c++) {
        if (c + 1 < nch) load_regs(c + 1);

        const char* stage = smem + (size_t)(c & 1) * 65536;
#pragma unroll
        for (int ks = 0; ks < 8; ks++) {
            const char* abase = stage + (ks >> 2) * 16384;
            const char* bbase = stage + 32768 + (ks >> 2) * 16384;
            const uint32_t c0 = col0[ks & 3], c1 = col1[ks & 3];
            uint32_t a[4][4], b[4][2];
#pragma unroll
            for (int mt = 0; mt < 4; mt++) {
                a[mt][0] = *(const uint32_t*)(abase + aoff[mt] + c0);
                a[mt][1] = *(const uint32_t*)(abase + aoff[mt] + 8 * 128 + c0);
                a[mt][2] = *(const uint32_t*)(abase + aoff[mt] + c1);
                a[mt][3] = *(const uint32_t*)(abase + aoff[mt] + 8 * 128 + c1);
            }
#pragma unroll
            for (int nt = 0; nt < 4; nt++) {
                b[nt][0] = *(const uint32_t*)(bbase + boff[nt] + c0);
                b[nt][1] = *(const uint32_t*)(bbase + boff[nt] + c1);
            }
#pragma unroll
            for (int mt = 0; mt < 4; mt++)
#pragma unroll
                for (int nt = 0; nt < 4; nt++)
                    mma_tf32(acc[mt][nt], a[mt], b[nt]);
        }

        if (c + 1 < nch) store_stage((c + 1) & 1);
        __syncthreads();
    }

    // ---- epilogue ----
    float* C;
    int nbase;
    if (BATCHN) {
        C = Cg + (size_t)(n0 >> 11) * sC;
        nbase = n0 & 2047;
    } else {
        C = Cg + (size_t)blockIdx.z * sC;
        nbase = n0;
    }
#pragma unroll
    for (int mt = 0; mt < 4; mt++) {
        const int m = m0 + warp_m + mt * 16 + g;
#pragma unroll
        for (int nt = 0; nt < 4; nt++) {
            const int n = nbase + warp_n + nt * 8 + tg * 2;
            float v00 = acc[mt][nt][0], v01 = acc[mt][nt][1];
            float v10 = acc[mt][nt][2], v11 = acc[mt][nt][3];
            if (BIASN) {
                const float b0 = bias[n0 - nbase + n], b1 = bias[n0 - nbase + n + 1];
                v00 += b0; v01 += b1;
                v10 += b0; v11 += b1;
            }
            if (BIASM) {
                const float bm0 = bias[m], bm1 = bias[m + 8];
                v00 += bm0; v01 += bm0;
                v10 += bm1; v11 += bm1;
            }
            if (ROUND) {
                v00 = tf32r(v00); v01 = tf32r(v01);
                v10 = tf32r(v10); v11 = tf32r(v11);
            }
            float* crow = C + (size_t)m * ldc + n;
            *(float2*)crow = make_float2(v00, v01);
            *(float2*)(crow + (size_t)8 * ldc) = make_float2(v10, v11);
        }
    }
}

// ---------------------------------------------------------------------------
// x -> tf32-rounded copy, fused with out[..., 0:512] = x
// ---------------------------------------------------------------------------
__global__ void cvt_x(const float4* __restrict__ in, float4* __restrict__ xr4,
                      float4* __restrict__ out4, int n4)
{
    const int i = blockIdx.x * blockDim.x + threadIdx.x;
    if (i >= n4) return;
    const float4 v = in[i];
    xr4[i] = make_float4(tf32r(v.x), tf32r(v.y), tf32r(v.z), tf32r(v.w));
    const size_t row = (size_t)i >> 7;
    const size_t col = (size_t)i & 127;
    out4[row * 256 + col] = v;
}

// 512x512 transpose + tf32 round: WT[n][k] = W[k][n]
__global__ void trans512cv(const float* __restrict__ W, float* __restrict__ WT)
{
    __shared__ float tile[32][33];
    const int tx = threadIdx.x & 31, ty = threadIdx.x >> 5;
    const int c0 = blockIdx.x * 32, r0 = blockIdx.y * 32;
#pragma unroll
    for (int r = 0; r < 4; r++)
        tile[ty + r * 8][tx] = W[(size_t)(r0 + ty + r * 8) * NC + c0 + tx];
    __syncthreads();
#pragma unroll
    for (int r = 0; r < 4; r++)
        WT[(size_t)(c0 + ty + r * 8) * NC + r0 + tx] = tf32r(tile[tx][ty + r * 8]);
}

// ---------------------------------------------------------------------------
// softmax pass 1: per key-column s, reduce over t >= s -> mx[s], 1/sum
// ---------------------------------------------------------------------------
__global__ void softmax_p1(const float* __restrict__ lg,
                           float* __restrict__ mx, float* __restrict__ inv)
{
    const int s = blockIdx.x, b = blockIdx.y;
    const float* row = lg + ((size_t)b * NT + s) * NT;
    __shared__ float red[256];
    const int tid = threadIdx.x;

    float lmax = -3.4e38f;
    for (int t = s + tid; t < NT; t += 256) lmax = fmaxf(lmax, row[t]);
    red[tid] = lmax;
    __syncthreads();
    for (int off = 128; off > 0; off >>= 1) {
        if (tid < off) red[tid] = fmaxf(red[tid], red[tid + off]);
        __syncthreads();
    }
    const float m = red[0] * SCALE;
    __syncthreads();

    float lsum = 0.f;
    for (int t = s + tid; t < NT; t += 256) lsum += __expf(row[t] * SCALE - m);
    red[tid] = lsum;
    __syncthreads();
    for (int off = 128; off > 0; off >>= 1) {
        if (tid < off) red[tid] += red[tid + off];
        __syncthreads();
    }
    if (tid == 0) {
        mx[b * NT + s]  = m;
        inv[b * NT + s] = 1.f / red[0];
    }
}

// ---------------------------------------------------------------------------
// softmax pass 2: exp + normalize + transpose -> P'[b][t][s] tf32-rounded
// ---------------------------------------------------------------------------
__global__ void softmax_p2(const float* __restrict__ lg, const float* __restrict__ mx,
                           const float* __restrict__ inv, float* __restrict__ P)
{
    const int ti = blockIdx.x, si = blockIdx.y, b = blockIdx.z;
    if (si * 32 >= ti * 32 + 128) return;   // never read by the read-GEMM
    __shared__ float tile[32][33];
    const int tx = threadIdx.x & 31, ty = threadIdx.x >> 5;
    const int t = ti * 32 + tx;
#pragma unroll
    for (int r = 0; r < 4; r++) {
        const int s = si * 32 + ty + r * 8;
        float p = 0.f;
        if (t >= s) {
            const float val = lg[((size_t)b * NT + s) * NT + t];
            p = __expf(val * SCALE - mx[b * NT + s]) * inv[b * NT + s];
        }
        tile[ty + r * 8][tx] = p;
    }
    __syncthreads();
    const int s2 = si * 32 + tx;
#pragma unroll
    for (int r = 0; r < 4; r++) {
        const int t2 = ti * 32 + ty + r * 8;
        P[((size_t)b * NT + t2) * NT + s2] = tf32r(tile[tx][ty + r * 8]);
    }
}

// ---------------------------------------------------------------------------
extern "C" void kernel_launch(void* const* d_in, const int* in_sizes, int n_in,
                              void* d_out, int out_size)
{
    const float* x  = (const float*)d_in[0];
    const float* Wq = (const float*)d_in[1];
    const float* bq = (const float*)d_in[2];
    const float* Wk = (const float*)d_in[3];
    const float* bk = (const float*)d_in[4];
    const float* Wv = (const float*)d_in[5];
    const float* bv = (const float*)d_in[6];
    float* out = (float*)d_out;

    float *xr, *wT, *q, *k, *vT, *lg, *p, *mx, *inv;
    cudaGetSymbolAddress((void**)&xr,  g_xr);
    cudaGetSymbolAddress((void**)&wT,  g_wT);
    cudaGetSymbolAddress((void**)&q,   g_q);
    cudaGetSymbolAddress((void**)&k,   g_k);
    cudaGetSymbolAddress((void**)&vT,  g_vT);
    cudaGetSymbolAddress((void**)&lg,  g_lg);
    cudaGetSymbolAddress((void**)&p,   g_p);
    cudaGetSymbolAddress((void**)&mx,  g_mx);
    cudaGetSymbolAddress((void**)&inv, g_inv);

    const int SMEM = 131072;
    cudaFuncSetAttribute(gemm_tf<true,  false, false, false, true,  false>, cudaFuncAttributeMaxDynamicSharedMemorySize, SMEM);
    cudaFuncSetAttribute(gemm_tf<false, true,  false, false, true,  true >, cudaFuncAttributeMaxDynamicSharedMemorySize, SMEM);
    cudaFuncSetAttribute(gemm_tf<false, false, true,  false, false, false>, cudaFuncAttributeMaxDynamicSharedMemorySize, SMEM);
    cudaFuncSetAttribute(gemm_tf<false, false, false, true,  false, false>, cudaFuncAttributeMaxDynamicSharedMemorySize, SMEM);

    const size_t strBT  = (size_t)NT * NC;
    const size_t strLG  = (size_t)NT * NT;
    const size_t strOUT = (size_t)NT * (2 * NC);

    // 0) operand prep: x -> tf32 (+ copy x to out); W -> transposed tf32
    cvt_x<<<(NB * NT * NC / 4 + 255) / 256, 256>>>(
        (const float4*)x, (float4*)xr, (float4*)out, NB * NT * NC / 4);
    trans512cv<<<dim3(16, 16), 256>>>(Wq, wT + 0 * NC * NC);
    trans512cv<<<dim3(16, 16), 256>>>(Wk, wT + 1 * NC * NC);
    trans512cv<<<dim3(16, 16), 256>>>(Wv, wT + 2 * NC * NC);

    // 1) Q,K projections (M=16384, N=512, K=512); outputs tf32-rounded
    {
        dim3 grid(NC / 128, (NB * NT) / 128, 1);
        gemm_tf<true, false, false, false, true, false><<<grid, 256, SMEM>>>(
            xr, wT + 0 * NC * NC, bq, q, NC, NC, NC, NC, 0, 0, 0);
        gemm_tf<true, false, false, false, true, false><<<grid, 256, SMEM>>>(
            xr, wT + 1 * NC * NC, bk, k, NC, NC, NC, NC, 0, 0, 0);
    }
    // 1v) V projection, transposed output: vT[b][c][t] = sum_k WvT[c][k] x[b,t,k] + bv[c]
    {
        dim3 grid((NB * NT) / 128, NC / 128, 1);   // n = global token, m = channel
        gemm_tf<false, true, false, false, true, true><<<grid, 256, SMEM>>>(
            wT + 2 * NC * NC, xr, bv, vT, NC, NC, NT, NC, 0, 0, (size_t)NC * NT);
    }

    // 2) logitsT[b][s][t] = sum_c k[b,s,c] * q[b,t,c]  (causal tile skip)
    {
        dim3 grid(NT / 128, NT / 128, NB);
        gemm_tf<false, false, true, false, false, false><<<grid, 256, SMEM>>>(
            k, q, nullptr, lg, NC, NC, NT, NC, strBT, strBT, strLG);
    }

    // 3) softmax over t (column softmax) -> P'[b][t][s] tf32-rounded
    softmax_p1<<<dim3(NT, NB), 256>>>(lg, mx, inv);
    softmax_p2<<<dim3(NT / 32, NT / 32, NB), 256>>>(lg, mx, inv, p);

    // 4) read[b][t][v] = sum_s P'[b,t,s] * vT[b,v,s]  -> out[..., 512:1024]
    {
        dim3 grid(NC / 128, NT / 128, NB);
        gemm_tf<false, false, false, true, false, false><<<grid, 256, SMEM>>>(
            p, vT, nullptr, out + NC, NT, NT, 2 * NC, NT,
            strLG, (size_t)NC * NT, strOUT);
    }
}

// round 10
// speedup vs baseline: 2.1940x; 1.1831x over previous
#include <cuda_runtime.h>
#include <cstdint>
#include <math.h>

#define NB 8
#define NT 2048
#define NC 512
#define SCALE 0.04419417382415922f   // 1/sqrt(512)

// ---------------- scratch (__device__ globals; allocation-free rule) --------
__device__ __align__(256) float g_xr [NB * NT * NC];          // x, tf32-rounded
__device__ __align__(256) float g_wT [3 * NC * NC];           // W^T, tf32-rounded
__device__ __align__(256) float g_q  [NB * NT * NC];          // tf32-rounded
__device__ __align__(256) float g_k  [NB * NT * NC];          // tf32-rounded
__device__ __align__(256) float g_vT [NB * NT * NC];          // tf32-rounded [b][c][t]
__device__ __align__(256) float g_lg [(size_t)NB * NT * NT];  // logitsT [b][s][t] fp32
__device__ __align__(256) float g_p  [(size_t)NB * NT * NT];  // P' [b][t][s] tf32-rounded
__device__ float g_mx [NB * NT];
__device__ float g_inv[NB * NT];

// ---------------- helpers ---------------------------------------------------
__device__ __forceinline__ uint32_t smem_u32(const void* p) {
    uint32_t a;
    asm("{ .reg .u64 t; cvta.to.shared.u64 t, %1; cvt.u32.u64 %0, t; }" : "=r"(a) : "l"(p));
    return a;
}
__device__ __forceinline__ float tf32r(float x) {
    float r;
    asm("cvt.rna.tf32.f32 %0, %1;" : "=f"(r) : "f"(x));
    return r;
}
__device__ __forceinline__ void mma_tf32(float* c, const uint32_t* a, const uint32_t* b) {
    asm volatile(
        "mma.sync.aligned.m16n8k8.row.col.f32.tf32.tf32.f32 "
        "{%0,%1,%2,%3}, {%4,%5,%6,%7}, {%8,%9}, {%0,%1,%2,%3};"
        : "+f"(c[0]), "+f"(c[1]), "+f"(c[2]), "+f"(c[3])
        : "r"(a[0]), "r"(a[1]), "r"(a[2]), "r"(a[3]), "r"(b[0]), "r"(b[1]));
}
__device__ __forceinline__ void cp16(uint32_t dst, const void* src) {
    asm volatile("cp.async.cg.shared.global [%0], [%1], 16;" :: "r"(dst), "l"(src));
}
#define CP_COMMIT() asm volatile("cp.async.commit_group;" ::: "memory")
#define CP_WAIT2()  asm volatile("cp.async.wait_group 2;" ::: "memory")

// ---------------------------------------------------------------------------
// Single-pass tf32 GEMM via mma.sync m16n8k8:
//   D[m][n] = sum_k A[m][k] * B[n][k]   (A,B fp32 pre-rounded to tf32)
// CTA tile 128x256, BK=32, 256 threads, warp tile 64x64 (2x4 warp grid).
// 4-stage cp.async(16B) pipeline; stage (48KB) = A 16KB (128 rows x 128B)
//   + B 32KB (256 rows x 128B); 16B chunk c of row r at r*128 + ((c^(r&7))<<4).
// Discipline: prologue commits stages 0..2; per iter: wait_group(2), sync,
//   issue load c+3 (slot freed at iter c-1), commit, compute c.
// CSKIP: skip tile if n0+255 < m0.  CKLIM: kend = min(K, m0+128).
// ROUND: tf32-round output.  BATCHN: n is global batched (b = n>>11).
// BIASN: bias[n].  BIASM: bias[m].
// ---------------------------------------------------------------------------
template<bool BIASN, bool BIASM, bool CSKIP, bool CKLIM, bool ROUND, bool BATCHN>
__global__ __launch_bounds__(256, 1)
void gemm_tf(const float* __restrict__ Ag, const float* __restrict__ Bg,
             const float* __restrict__ bias, float* __restrict__ Cg,
             int lda, int ldb, int ldc, int Ktot,
             size_t sA, size_t sB, size_t sC)
{
    extern __shared__ char smem[];
    const int m0 = blockIdx.y * 128;
    const int n0 = blockIdx.x * 256;
    if (CSKIP && (n0 + 255) < m0) return;

    const float* A = Ag + (size_t)blockIdx.z * sA;
    const float* B = Bg + (size_t)blockIdx.z * sB;

    const int tid = threadIdx.x;
    const int lane = tid & 31;
    const int wid = tid >> 5;
    const int warp_m = (wid & 1) * 64;
    const int warp_n = (wid >> 1) * 64;
    const int g  = lane >> 2;    // 0..7
    const int tg = lane & 3;     // 0..3
    const uint32_t smem_u = smem_u32(smem);

    // fragment column offsets within a 128B row (16B-chunk XOR swizzle)
    uint32_t col0[4], col1[4];
#pragma unroll
    for (int j = 0; j < 4; j++) {
        col0[j] = (((uint32_t)((2 * j)     ^ g)) << 4) + (uint32_t)tg * 4;
        col1[j] = (((uint32_t)((2 * j + 1) ^ g)) << 4) + (uint32_t)tg * 4;
    }
    uint32_t aoff[4], boff[8];
#pragma unroll
    for (int mt = 0; mt < 4; mt++)
        aoff[mt] = (uint32_t)(warp_m + mt * 16 + g) * 128;
#pragma unroll
    for (int nt = 0; nt < 8; nt++)
        boff[nt] = 16384u + (uint32_t)(warp_n + nt * 8 + g) * 128;

    // loader: lc = 16B chunk 0..7 within row, lr = row base 0..31
    const int lc = tid & 7;
    const int lr = tid >> 3;

    float acc[4][8][4];
#pragma unroll
    for (int mt = 0; mt < 4; mt++)
#pragma unroll
        for (int nt = 0; nt < 8; nt++)
#pragma unroll
            for (int r = 0; r < 4; r++) acc[mt][nt][r] = 0.f;

    const int kend = CKLIM ? min(Ktot, m0 + 128) : Ktot;
    const int nch = kend >> 5;   // BK = 32; >= 4 always here

    auto load_stage = [&](int slot, int chunk) {
        const uint32_t sbase = smem_u + (uint32_t)slot * 49152u;
        const int k0 = (chunk << 5) + lc * 4;
#pragma unroll
        for (int i = 0; i < 4; i++) {   // A: 128 rows
            const int r = lr + i * 32;
            const uint32_t off = (uint32_t)r * 128 + ((uint32_t)(lc ^ (r & 7)) << 4);
            cp16(sbase + off, A + (size_t)(m0 + r) * lda + k0);
        }
#pragma unroll
        for (int i = 0; i < 8; i++) {   // B: 256 rows
            const int r = lr + i * 32;
            const uint32_t off = (uint32_t)r * 128 + ((uint32_t)(lc ^ (r & 7)) << 4);
            cp16(sbase + 16384u + off, B + (size_t)(n0 + r) * ldb + k0);
        }
    };

    // prologue: stages 0..2 (nch >= 4 guaranteed)
#pragma unroll
    for (int s = 0; s < 3; s++) {
        load_stage(s, s);
        CP_COMMIT();
    }

    for (int c = 0; c < nch; c++) {
        CP_WAIT2();          // commits = c+3 ; completed >= c+1  => chunk c ready
        __syncthreads();     // all warps done computing chunk c-1 (slot c+3 target)
        if (c + 3 < nch) load_stage((c + 3) & 3, c + 3);
        CP_COMMIT();

        const char* stage = smem + (size_t)(c & 3) * 49152;
#pragma unroll
        for (int ks = 0; ks < 4; ks++) {
            const uint32_t c0 = col0[ks], c1 = col1[ks];
            uint32_t a[4][4], b[8][2];
#pragma unroll
            for (int mt = 0; mt < 4; mt++) {
                a[mt][0] = *(const uint32_t*)(stage + aoff[mt] + c0);
                a[mt][1] = *(const uint32_t*)(stage + aoff[mt] + 8 * 128 + c0);
                a[mt][2] = *(const uint32_t*)(stage + aoff[mt] + c1);
                a[mt][3] = *(const uint32_t*)(stage + aoff[mt] + 8 * 128 + c1);
            }
#pragma unroll
            for (int nt = 0; nt < 8; nt++) {
                b[nt][0] = *(const uint32_t*)(stage + boff[nt] + c0);
                b[nt][1] = *(const uint32_t*)(stage + boff[nt] + c1);
            }
#pragma unroll
            for (int mt = 0; mt < 4; mt++)
#pragma unroll
                for (int nt = 0; nt < 8; nt++)
                    mma_tf32(acc[mt][nt], a[mt], b[nt]);
        }
    }

    // ---- epilogue ----
    float* C;
    int nbase;
    if (BATCHN) {
        C = Cg + (size_t)(n0 >> 11) * sC;
        nbase = n0 & 2047;
    } else {
        C = Cg + (size_t)blockIdx.z * sC;
        nbase = n0;
    }
#pragma unroll
    for (int mt = 0; mt < 4; mt++) {
        const int m = m0 + warp_m + mt * 16 + g;
#pragma unroll
        for (int nt = 0; nt < 8; nt++) {
            const int n = nbase + warp_n + nt * 8 + tg * 2;
            float v00 = acc[mt][nt][0], v01 = acc[mt][nt][1];
            float v10 = acc[mt][nt][2], v11 = acc[mt][nt][3];
            if (BIASN) {
                const float b0 = bias[n0 - nbase + n], b1 = bias[n0 - nbase + n + 1];
                v00 += b0; v01 += b1;
                v10 += b0; v11 += b1;
            }
            if (BIASM) {
                const float bm0 = bias[m], bm1 = bias[m + 8];
                v00 += bm0; v01 += bm0;
                v10 += bm1; v11 += bm1;
            }
            if (ROUND) {
                v00 = tf32r(v00); v01 = tf32r(v01);
                v10 = tf32r(v10); v11 = tf32r(v11);
            }
            float* crow = C + (size_t)m * ldc + n;
            *(float2*)crow = make_float2(v00, v01);
            *(float2*)(crow + (size_t)8 * ldc) = make_float2(v10, v11);
        }
    }
}

// ---------------------------------------------------------------------------
// x -> tf32-rounded copy, fused with out[..., 0:512] = x
// ---------------------------------------------------------------------------
__global__ void cvt_x(const float4* __restrict__ in, float4* __restrict__ xr4,
                      float4* __restrict__ out4, int n4)
{
    const int i = blockIdx.x * blockDim.x + threadIdx.x;
    if (i >= n4) return;
    const float4 v = in[i];
    xr4[i] = make_float4(tf32r(v.x), tf32r(v.y), tf32r(v.z), tf32r(v.w));
    const size_t row = (size_t)i >> 7;
    const size_t col = (size_t)i & 127;
    out4[row * 256 + col] = v;
}

// 512x512 transpose + tf32 round: WT[n][k] = W[k][n]
__global__ void trans512cv(const float* __restrict__ W, float* __restrict__ WT)
{
    __shared__ float tile[32][33];
    const int tx = threadIdx.x & 31, ty = threadIdx.x >> 5;
    const int c0 = blockIdx.x * 32, r0 = blockIdx.y * 32;
#pragma unroll
    for (int r = 0; r < 4; r++)
        tile[ty + r * 8][tx] = W[(size_t)(r0 + ty + r * 8) * NC + c0 + tx];
    __syncthreads();
#pragma unroll
    for (int r = 0; r < 4; r++)
        WT[(size_t)(c0 + ty + r * 8) * NC + r0 + tx] = tf32r(tile[tx][ty + r * 8]);
}

// ---------------------------------------------------------------------------
// softmax pass 1: per key-column s, reduce over t >= s -> mx[s], 1/sum
// ---------------------------------------------------------------------------
__global__ void softmax_p1(const float* __restrict__ lg,
                           float* __restrict__ mx, float* __restrict__ inv)
{
    const int s = blockIdx.x, b = blockIdx.y;
    const float* row = lg + ((size_t)b * NT + s) * NT;
    __shared__ float red[256];
    const int tid = threadIdx.x;

    float lmax = -3.4e38f;
    for (int t = s + tid; t < NT; t += 256) lmax = fmaxf(lmax, row[t]);
    red[tid] = lmax;
    __syncthreads();
    for (int off = 128; off > 0; off >>= 1) {
        if (tid < off) red[tid] = fmaxf(red[tid], red[tid + off]);
        __syncthreads();
    }
    const float m = red[0] * SCALE;
    __syncthreads();

    float lsum = 0.f;
    for (int t = s + tid; t < NT; t += 256) lsum += __expf(row[t] * SCALE - m);
    red[tid] = lsum;
    __syncthreads();
    for (int off = 128; off > 0; off >>= 1) {
        if (tid < off) red[tid] += red[tid + off];
        __syncthreads();
    }
    if (tid == 0) {
        mx[b * NT + s]  = m;
        inv[b * NT + s] = 1.f / red[0];
    }
}

// ---------------------------------------------------------------------------
// softmax pass 2: exp + normalize + transpose -> P'[b][t][s] tf32-rounded
// ---------------------------------------------------------------------------
__global__ void softmax_p2(const float* __restrict__ lg, const float* __restrict__ mx,
                           const float* __restrict__ inv, float* __restrict__ P)
{
    const int ti = blockIdx.x, si = blockIdx.y, b = blockIdx.z;
    if (si * 32 >= ti * 32 + 128) return;   // never read by the read-GEMM
    __shared__ float tile[32][33];
    const int tx = threadIdx.x & 31, ty = threadIdx.x >> 5;
    const int t = ti * 32 + tx;
#pragma unroll
    for (int r = 0; r < 4; r++) {
        const int s = si * 32 + ty + r * 8;
        float p = 0.f;
        if (t >= s) {
            const float val = lg[((size_t)b * NT + s) * NT + t];
            p = __expf(val * SCALE - mx[b * NT + s]) * inv[b * NT + s];
        }
        tile[ty + r * 8][tx] = p;
    }
    __syncthreads();
    const int s2 = si * 32 + tx;
#pragma unroll
    for (int r = 0; r < 4; r++) {
        const int t2 = ti * 32 + ty + r * 8;
        P[((size_t)b * NT + t2) * NT + s2] = tf32r(tile[tx][ty + r * 8]);
    }
}

// ---------------------------------------------------------------------------
extern "C" void kernel_launch(void* const* d_in, const int* in_sizes, int n_in,
                              void* d_out, int out_size)
{
    const float* x  = (const float*)d_in[0];
    const float* Wq = (const float*)d_in[1];
    const float* bq = (const float*)d_in[2];
    const float* Wk = (const float*)d_in[3];
    const float* bk = (const float*)d_in[4];
    const float* Wv = (const float*)d_in[5];
    const float* bv = (const float*)d_in[6];
    float* out = (float*)d_out;

    float *xr, *wT, *q, *k, *vT, *lg, *p, *mx, *inv;
    cudaGetSymbolAddress((void**)&xr,  g_xr);
    cudaGetSymbolAddress((void**)&wT,  g_wT);
    cudaGetSymbolAddress((void**)&q,   g_q);
    cudaGetSymbolAddress((void**)&k,   g_k);
    cudaGetSymbolAddress((void**)&vT,  g_vT);
    cudaGetSymbolAddress((void**)&lg,  g_lg);
    cudaGetSymbolAddress((void**)&p,   g_p);
    cudaGetSymbolAddress((void**)&mx,  g_mx);
    cudaGetSymbolAddress((void**)&inv, g_inv);

    const int SMEM = 4 * 49152;   // 196608
    cudaFuncSetAttribute(gemm_tf<true,  false, false, false, true,  false>, cudaFuncAttributeMaxDynamicSharedMemorySize, SMEM);
    cudaFuncSetAttribute(gemm_tf<false, true,  false, false, true,  true >, cudaFuncAttributeMaxDynamicSharedMemorySize, SMEM);
    cudaFuncSetAttribute(gemm_tf<false, false, true,  false, false, false>, cudaFuncAttributeMaxDynamicSharedMemorySize, SMEM);
    cudaFuncSetAttribute(gemm_tf<false, false, false, true,  false, false>, cudaFuncAttributeMaxDynamicSharedMemorySize, SMEM);

    const size_t strBT  = (size_t)NT * NC;
    const size_t strLG  = (size_t)NT * NT;
    const size_t strOUT = (size_t)NT * (2 * NC);

    // 0) operand prep: x -> tf32 (+ copy x to out); W -> transposed tf32
    cvt_x<<<(NB * NT * NC / 4 + 255) / 256, 256>>>(
        (const float4*)x, (float4*)xr, (float4*)out, NB * NT * NC / 4);
    trans512cv<<<dim3(16, 16), 256>>>(Wq, wT + 0 * NC * NC);
    trans512cv<<<dim3(16, 16), 256>>>(Wk, wT + 1 * NC * NC);
    trans512cv<<<dim3(16, 16), 256>>>(Wv, wT + 2 * NC * NC);

    // 1) Q,K projections (M=16384, N=512, K=512); outputs tf32-rounded
    {
        dim3 grid(NC / 256, (NB * NT) / 128, 1);
        gemm_tf<true, false, false, false, true, false><<<grid, 256, SMEM>>>(
            xr, wT + 0 * NC * NC, bq, q, NC, NC, NC, NC, 0, 0, 0);
        gemm_tf<true, false, false, false, true, false><<<grid, 256, SMEM>>>(
            xr, wT + 1 * NC * NC, bk, k, NC, NC, NC, NC, 0, 0, 0);
    }
    // 1v) V projection, transposed output: vT[b][c][t] = sum_k WvT[c][k] x[b,t,k] + bv[c]
    {
        dim3 grid((NB * NT) / 256, NC / 128, 1);   // n = global token, m = channel
        gemm_tf<false, true, false, false, true, true><<<grid, 256, SMEM>>>(
            wT + 2 * NC * NC, xr, bv, vT, NC, NC, NT, NC, 0, 0, (size_t)NC * NT);
    }

    // 2) logitsT[b][s][t] = sum_c k[b,s,c] * q[b,t,c]  (causal tile skip)
    {
        dim3 grid(NT / 256, NT / 128, NB);
        gemm_tf<false, false, true, false, false, false><<<grid, 256, SMEM>>>(
            k, q, nullptr, lg, NC, NC, NT, NC, strBT, strBT, strLG);
    }

    // 3) softmax over t (column softmax) -> P'[b][t][s] tf32-rounded
    softmax_p1<<<dim3(NT, NB), 256>>>(lg, mx, inv);
    softmax_p2<<<dim3(NT / 32, NT / 32, NB), 256>>>(lg, mx, inv, p);

    // 4) read[b][t][v] = sum_s P'[b,t,s] * vT[b,v,s]  -> out[..., 512:1024]
    {
        dim3 grid(NC / 256, NT / 128, NB);
        gemm_tf<false, false, false, true, false, false><<<grid, 256, SMEM>>>(
            p, vT, nullptr, out + NC, NT, NT, 2 * NC, NT,
            strLG, (size_t)NC * NT, strOUT);
    }
}

// round 11
// speedup vs baseline: 3.4232x; 1.5603x over previous
#include <cuda_runtime.h>
#include <cuda_fp16.h>
#include <cstdint>
#include <math.h>

#define NB 8
#define NT 2048
#define NC 512
#define SCALE 0.04419417382415922f   // 1/sqrt(512)

// ---------------- scratch (__device__ globals; allocation-free rule) --------
__device__ __align__(256) __half g_xr [NB * NT * NC];          // x, fp16
__device__ __align__(256) __half g_wT [3 * NC * NC];           // W^T, fp16
__device__ __align__(256) __half g_q  [NB * NT * NC];          // fp16
__device__ __align__(256) __half g_k  [NB * NT * NC];          // fp16
__device__ __align__(256) __half g_vT [NB * NT * NC];          // fp16 [b][c][t]
__device__ __align__(256) __half g_p  [(size_t)NB * NT * NT];  // P' [b][t][s] fp16
__device__ __align__(256) float  g_lg [(size_t)NB * NT * NT];  // logitsT [b][s][t] fp32
__device__ float g_mx [NB * NT];
__device__ float g_inv[NB * NT];

// ---------------- helpers ---------------------------------------------------
__device__ __forceinline__ uint32_t smem_u32(const void* p) {
    uint32_t a;
    asm("{ .reg .u64 t; cvta.to.shared.u64 t, %1; cvt.u32.u64 %0, t; }" : "=r"(a) : "l"(p));
    return a;
}
__device__ __forceinline__ void mma_f16(float* c, const uint32_t* a, const uint32_t* b) {
    asm volatile(
        "mma.sync.aligned.m16n8k16.row.col.f32.f16.f16.f32 "
        "{%0,%1,%2,%3}, {%4,%5,%6,%7}, {%8,%9}, {%0,%1,%2,%3};"
        : "+f"(c[0]), "+f"(c[1]), "+f"(c[2]), "+f"(c[3])
        : "r"(a[0]), "r"(a[1]), "r"(a[2]), "r"(a[3]), "r"(b[0]), "r"(b[1]));
}
__device__ __forceinline__ void cp16(uint32_t dst, const void* src) {
    asm volatile("cp.async.cg.shared.global [%0], [%1], 16;" :: "r"(dst), "l"(src));
}
#define CP_COMMIT() asm volatile("cp.async.commit_group;" ::: "memory")
#define CP_WAIT2()  asm volatile("cp.async.wait_group 2;" ::: "memory")

// ---------------------------------------------------------------------------
// fp16-input / fp32-accum GEMM via mma.sync m16n8k16:
//   D[m][n] = sum_k A[m][k] * B[n][k]   (A,B __half, k-contiguous)
// CTA tile 128x256, BK=64 halfs, 256 threads, warp tile 64x64 (2x4 warps).
// 4-stage cp.async(16B) pipeline; stage (48KB) = A 16KB (128 rows x 128B)
//   + B 32KB (256 rows x 128B); 16B chunk c of row r at r*128 + ((c^(r&7))<<4).
// Per iter: wait_group(2), sync, issue load c+3, commit, compute chunk c.
// CSKIP: skip tile if n0+255 < m0.  CKLIM: kend = min(K, m0+128).
// OUTH: write C as __half (half2 stores).  BATCHN: n globally batched.
// BIASN: bias[n].  BIASM: bias[m].
// ---------------------------------------------------------------------------
template<bool BIASN, bool BIASM, bool CSKIP, bool CKLIM, bool OUTH, bool BATCHN>
__global__ __launch_bounds__(256, 1)
void gemm_h(const __half* __restrict__ Ag, const __half* __restrict__ Bg,
            const float* __restrict__ bias, float* __restrict__ Cf,
            __half* __restrict__ Ch,
            int lda, int ldb, int ldc, int Ktot,
            size_t sA, size_t sB, size_t sC)
{
    extern __shared__ char smem[];
    const int m0 = blockIdx.y * 128;
    const int n0 = blockIdx.x * 256;
    if (CSKIP && (n0 + 255) < m0) return;

    const __half* A = Ag + (size_t)blockIdx.z * sA;
    const __half* B = Bg + (size_t)blockIdx.z * sB;

    const int tid = threadIdx.x;
    const int lane = tid & 31;
    const int wid = tid >> 5;
    const int warp_m = (wid & 1) * 64;
    const int warp_n = (wid >> 1) * 64;
    const int g  = lane >> 2;    // 0..7
    const int tg = lane & 3;     // 0..3
    const uint32_t smem_u = smem_u32(smem);

    // fragment column offsets within a 128B row (16B-chunk XOR swizzle)
    // k16-step ks covers 32B = chunks 2ks (k0..7) and 2ks+1 (k8..15)
    uint32_t col0[4], col1[4];
#pragma unroll
    for (int j = 0; j < 4; j++) {
        col0[j] = (((uint32_t)((2 * j)     ^ g)) << 4) + (uint32_t)tg * 4;
        col1[j] = (((uint32_t)((2 * j + 1) ^ g)) << 4) + (uint32_t)tg * 4;
    }
    uint32_t aoff[4], boff[8];
#pragma unroll
    for (int mt = 0; mt < 4; mt++)
        aoff[mt] = (uint32_t)(warp_m + mt * 16 + g) * 128;
#pragma unroll
    for (int nt = 0; nt < 8; nt++)
        boff[nt] = 16384u + (uint32_t)(warp_n + nt * 8 + g) * 128;

    // loader: lc = 16B chunk 0..7 within row, lr = row base 0..31
    const int lc = tid & 7;
    const int lr = tid >> 3;

    float acc[4][8][4];
#pragma unroll
    for (int mt = 0; mt < 4; mt++)
#pragma unroll
        for (int nt = 0; nt < 8; nt++)
#pragma unroll
            for (int r = 0; r < 4; r++) acc[mt][nt][r] = 0.f;

    const int kend = CKLIM ? min(Ktot, m0 + 128) : Ktot;
    const int nch = kend >> 6;   // BK = 64 halfs; >= 2 always here

    auto load_stage = [&](int slot, int chunk) {
        const uint32_t sbase = smem_u + (uint32_t)slot * 49152u;
        const int k0 = (chunk << 6) + lc * 8;   // halfs
#pragma unroll
        for (int i = 0; i < 4; i++) {   // A: 128 rows
            const int r = lr + i * 32;
            const uint32_t off = (uint32_t)r * 128 + ((uint32_t)(lc ^ (r & 7)) << 4);
            cp16(sbase + off, A + (size_t)(m0 + r) * lda + k0);
        }
#pragma unroll
        for (int i = 0; i < 8; i++) {   // B: 256 rows
            const int r = lr + i * 32;
            const uint32_t off = (uint32_t)r * 128 + ((uint32_t)(lc ^ (r & 7)) << 4);
            cp16(sbase + 16384u + off, B + (size_t)(n0 + r) * ldb + k0);
        }
    };

    // prologue: stages 0..2 (guard for short K; commit unconditionally)
#pragma unroll
    for (int s = 0; s < 3; s++) {
        if (s < nch) load_stage(s, s);
        CP_COMMIT();
    }

    for (int c = 0; c < nch; c++) {
        CP_WAIT2();          // commits = c+3 ; completed >= c+1  => chunk c ready
        __syncthreads();     // all warps done with chunk c-1 (slot c+3 target)
        if (c + 3 < nch) load_stage((c + 3) & 3, c + 3);
        CP_COMMIT();

        const char* stage = smem + (size_t)(c & 3) * 49152;
#pragma unroll
        for (int ks = 0; ks < 4; ks++) {
            const uint32_t c0 = col0[ks], c1 = col1[ks];
            uint32_t a[4][4], b[8][2];
#pragma unroll
            for (int mt = 0; mt < 4; mt++) {
                a[mt][0] = *(const uint32_t*)(stage + aoff[mt] + c0);
                a[mt][1] = *(const uint32_t*)(stage + aoff[mt] + 8 * 128 + c0);
                a[mt][2] = *(const uint32_t*)(stage + aoff[mt] + c1);
                a[mt][3] = *(const uint32_t*)(stage + aoff[mt] + 8 * 128 + c1);
            }
#pragma unroll
            for (int nt = 0; nt < 8; nt++) {
                b[nt][0] = *(const uint32_t*)(stage + boff[nt] + c0);
                b[nt][1] = *(const uint32_t*)(stage + boff[nt] + c1);
            }
#pragma unroll
            for (int mt = 0; mt < 4; mt++)
#pragma unroll
                for (int nt = 0; nt < 8; nt++)
                    mma_f16(acc[mt][nt], a[mt], b[nt]);
        }
    }

    // ---- epilogue ----
    int nbase;
    size_t cofs;
    if (BATCHN) {
        cofs = (size_t)(n0 >> 11) * sC;
        nbase = n0 & 2047;
    } else {
        cofs = (size_t)blockIdx.z * sC;
        nbase = n0;
    }
#pragma unroll
    for (int mt = 0; mt < 4; mt++) {
        const int m = m0 + warp_m + mt * 16 + g;
#pragma unroll
        for (int nt = 0; nt < 8; nt++) {
            const int n = nbase + warp_n + nt * 8 + tg * 2;
            float v00 = acc[mt][nt][0], v01 = acc[mt][nt][1];
            float v10 = acc[mt][nt][2], v11 = acc[mt][nt][3];
            if (BIASN) {
                const float b0 = bias[n0 - nbase + n], b1 = bias[n0 - nbase + n + 1];
                v00 += b0; v01 += b1;
                v10 += b0; v11 += b1;
            }
            if (BIASM) {
                const float bm0 = bias[m], bm1 = bias[m + 8];
                v00 += bm0; v01 += bm0;
                v10 += bm1; v11 += bm1;
            }
            if (OUTH) {
                __half* crow = Ch + cofs + (size_t)m * ldc + n;
                *(__half2*)crow = __floats2half2_rn(v00, v01);
                *(__half2*)(crow + (size_t)8 * ldc) = __floats2half2_rn(v10, v11);
            } else {
                float* crow = Cf + cofs + (size_t)m * ldc + n;
                *(float2*)crow = make_float2(v00, v01);
                *(float2*)(crow + (size_t)8 * ldc) = make_float2(v10, v11);
            }
        }
    }
}

// ---------------------------------------------------------------------------
// x -> fp16 copy, fused with out[..., 0:512] = x
// ---------------------------------------------------------------------------
__global__ void cvt_x(const float4* __restrict__ in, __half2* __restrict__ xh2,
                      float4* __restrict__ out4, int n4)
{
    const int i = blockIdx.x * blockDim.x + threadIdx.x;
    if (i >= n4) return;
    const float4 v = in[i];
    xh2[2 * i + 0] = __floats2half2_rn(v.x, v.y);
    xh2[2 * i + 1] = __floats2half2_rn(v.z, v.w);
    const size_t row = (size_t)i >> 7;
    const size_t col = (size_t)i & 127;
    out4[row * 256 + col] = v;
}

// 512x512 transpose + fp16: WT[n][k] = W[k][n]
__global__ void trans512cv(const float* __restrict__ W, __half* __restrict__ WT)
{
    __shared__ float tile[32][33];
    const int tx = threadIdx.x & 31, ty = threadIdx.x >> 5;
    const int c0 = blockIdx.x * 32, r0 = blockIdx.y * 32;
#pragma unroll
    for (int r = 0; r < 4; r++)
        tile[ty + r * 8][tx] = W[(size_t)(r0 + ty + r * 8) * NC + c0 + tx];
    __syncthreads();
#pragma unroll
    for (int r = 0; r < 4; r++)
        WT[(size_t)(c0 + ty + r * 8) * NC + r0 + tx] = __float2half_rn(tile[tx][ty + r * 8]);
}

// ---------------------------------------------------------------------------
// softmax pass 1: per key-column s, reduce over t >= s -> mx[s], 1/sum
// ---------------------------------------------------------------------------
__global__ void softmax_p1(const float* __restrict__ lg,
                           float* __restrict__ mx, float* __restrict__ inv)
{
    const int s = blockIdx.x, b = blockIdx.y;
    const float* row = lg + ((size_t)b * NT + s) * NT;
    __shared__ float red[256];
    const int tid = threadIdx.x;

    float lmax = -3.4e38f;
    for (int t = s + tid; t < NT; t += 256) lmax = fmaxf(lmax, row[t]);
    red[tid] = lmax;
    __syncthreads();
    for (int off = 128; off > 0; off >>= 1) {
        if (tid < off) red[tid] = fmaxf(red[tid], red[tid + off]);
        __syncthreads();
    }
    const float m = red[0] * SCALE;
    __syncthreads();

    float lsum = 0.f;
    for (int t = s + tid; t < NT; t += 256) lsum += __expf(row[t] * SCALE - m);
    red[tid] = lsum;
    __syncthreads();
    for (int off = 128; off > 0; off >>= 1) {
        if (tid < off) red[tid] += red[tid + off];
        __syncthreads();
    }
    if (tid == 0) {
        mx[b * NT + s]  = m;
        inv[b * NT + s] = 1.f / red[0];
    }
}

// ---------------------------------------------------------------------------
// softmax pass 2: exp + normalize + transpose -> P'[b][t][s] fp16
// ---------------------------------------------------------------------------
__global__ void softmax_p2(const float* __restrict__ lg, const float* __restrict__ mx,
                           const float* __restrict__ inv, __half* __restrict__ P)
{
    const int ti = blockIdx.x, si = blockIdx.y, b = blockIdx.z;
    if (si * 32 >= ti * 32 + 128) return;   // never read by the read-GEMM
    __shared__ float tile[32][33];
    const int tx = threadIdx.x & 31, ty = threadIdx.x >> 5;
    const int t = ti * 32 + tx;
#pragma unroll
    for (int r = 0; r < 4; r++) {
        const int s = si * 32 + ty + r * 8;
        float p = 0.f;
        if (t >= s) {
            const float val = lg[((size_t)b * NT + s) * NT + t];
            p = __expf(val * SCALE - mx[b * NT + s]) * inv[b * NT + s];
        }
        tile[ty + r * 8][tx] = p;
    }
    __syncthreads();
    const int s2 = si * 32 + tx;
#pragma unroll
    for (int r = 0; r < 4; r++) {
        const int t2 = ti * 32 + ty + r * 8;
        P[((size_t)b * NT + t2) * NT + s2] = __float2half_rn(tile[tx][ty + r * 8]);
    }
}

// ---------------------------------------------------------------------------
extern "C" void kernel_launch(void* const* d_in, const int* in_sizes, int n_in,
                              void* d_out, int out_size)
{
    const float* x  = (const float*)d_in[0];
    const float* Wq = (const float*)d_in[1];
    const float* bq = (const float*)d_in[2];
    const float* Wk = (const float*)d_in[3];
    const float* bk = (const float*)d_in[4];
    const float* Wv = (const float*)d_in[5];
    const float* bv = (const float*)d_in[6];
    float* out = (float*)d_out;

    __half *xr, *wT, *q, *k, *vT, *p;
    float *lg, *mx, *inv;
    cudaGetSymbolAddress((void**)&xr,  g_xr);
    cudaGetSymbolAddress((void**)&wT,  g_wT);
    cudaGetSymbolAddress((void**)&q,   g_q);
    cudaGetSymbolAddress((void**)&k,   g_k);
    cudaGetSymbolAddress((void**)&vT,  g_vT);
    cudaGetSymbolAddress((void**)&p,   g_p);
    cudaGetSymbolAddress((void**)&lg,  g_lg);
    cudaGetSymbolAddress((void**)&mx,  g_mx);
    cudaGetSymbolAddress((void**)&inv, g_inv);

    const int SMEM = 4 * 49152;   // 196608
    cudaFuncSetAttribute(gemm_h<true,  false, false, false, true,  false>, cudaFuncAttributeMaxDynamicSharedMemorySize, SMEM);
    cudaFuncSetAttribute(gemm_h<false, true,  false, false, true,  true >, cudaFuncAttributeMaxDynamicSharedMemorySize, SMEM);
    cudaFuncSetAttribute(gemm_h<false, false, true,  false, false, false>, cudaFuncAttributeMaxDynamicSharedMemorySize, SMEM);
    cudaFuncSetAttribute(gemm_h<false, false, false, true,  false, false>, cudaFuncAttributeMaxDynamicSharedMemorySize, SMEM);

    const size_t strBT  = (size_t)NT * NC;
    const size_t strLG  = (size_t)NT * NT;
    const size_t strOUT = (size_t)NT * (2 * NC);

    // 0) operand prep: x -> fp16 (+ copy x to out); W -> transposed fp16
    cvt_x<<<(NB * NT * NC / 4 + 255) / 256, 256>>>(
        (const float4*)x, (__half2*)xr, (float4*)out, NB * NT * NC / 4);
    trans512cv<<<dim3(16, 16), 256>>>(Wq, wT + 0 * NC * NC);
    trans512cv<<<dim3(16, 16), 256>>>(Wk, wT + 1 * NC * NC);
    trans512cv<<<dim3(16, 16), 256>>>(Wv, wT + 2 * NC * NC);

    // 1) Q,K projections (M=16384, N=512, K=512); outputs fp16
    {
        dim3 grid(NC / 256, (NB * NT) / 128, 1);
        gemm_h<true, false, false, false, true, false><<<grid, 256, SMEM>>>(
            xr, wT + 0 * NC * NC, bq, nullptr, q, NC, NC, NC, NC, 0, 0, 0);
        gemm_h<true, false, false, false, true, false><<<grid, 256, SMEM>>>(
            xr, wT + 1 * NC * NC, bk, nullptr, k, NC, NC, NC, NC, 0, 0, 0);
    }
    // 1v) V projection, transposed: vT[b][c][t] = sum_k WvT[c][k] x[b,t,k] + bv[c]
    {
        dim3 grid((NB * NT) / 256, NC / 128, 1);   // n = global token, m = channel
        gemm_h<false, true, false, false, true, true><<<grid, 256, SMEM>>>(
            wT + 2 * NC * NC, xr, bv, nullptr, vT, NC, NC, NT, NC, 0, 0, (size_t)NC * NT);
    }

    // 2) logitsT[b][s][t] = sum_c k[b,s,c] * q[b,t,c]  (causal tile skip)
    {
        dim3 grid(NT / 256, NT / 128, NB);
        gemm_h<false, false, true, false, false, false><<<grid, 256, SMEM>>>(
            k, q, nullptr, lg, nullptr, NC, NC, NT, NC, strBT, strBT, strLG);
    }

    // 3) softmax over t (column softmax) -> P'[b][t][s] fp16
    softmax_p1<<<dim3(NT, NB), 256>>>(lg, mx, inv);
    softmax_p2<<<dim3(NT / 32, NT / 32, NB), 256>>>(lg, mx, inv, p);

    // 4) read[b][t][v] = sum_s P'[b,t,s] * vT[b,v,s]  -> out[..., 512:1024]
    {
        dim3 grid(NC / 256, NT / 128, NB);
        gemm_h<false, false, false, true, false, false><<<grid, 256, SMEM>>>(
            p, vT, nullptr, out + NC, nullptr, NT, NT, 2 * NC, NT,
            strLG, (size_t)NC * NT, strOUT);
    }
}

// round 12
// speedup vs baseline: 4.0532x; 1.1841x over previous
#include <cuda_runtime.h>
#include <cuda_fp16.h>
#include <cstdint>
#include <math.h>

#define NB 8
#define NT 2048
#define NC 512
#define SCALE 0.04419417382415922f   // 1/sqrt(512)

// ---------------- scratch (__device__ globals; allocation-free rule) --------
__device__ __align__(256) __half g_xr [NB * NT * NC];          // x, fp16
__device__ __align__(256) __half g_wT [3 * NC * NC];           // W^T, fp16
__device__ __align__(256) __half g_q  [NB * NT * NC];          // fp16
__device__ __align__(256) __half g_k  [NB * NT * NC];          // fp16
__device__ __align__(256) __half g_vT [NB * NT * NC];          // fp16 [b][c][t]
__device__ __align__(256) __half g_p  [(size_t)NB * NT * NT];  // P=exp [b][t][s] fp16
__device__ __align__(256) float  g_zpart[16 * NB * NT];        // per-t-tile Z partials
__device__ __align__(256) float  g_zinv [NB * NT];             // 1/Z[s]

// ---------------- helpers ---------------------------------------------------
__device__ __forceinline__ uint32_t smem_u32(const void* p) {
    uint32_t a;
    asm("{ .reg .u64 t; cvta.to.shared.u64 t, %1; cvt.u32.u64 %0, t; }" : "=r"(a) : "l"(p));
    return a;
}
__device__ __forceinline__ void mma_f16(float* c, const uint32_t* a, const uint32_t* b) {
    asm volatile(
        "mma.sync.aligned.m16n8k16.row.col.f32.f16.f16.f32 "
        "{%0,%1,%2,%3}, {%4,%5,%6,%7}, {%8,%9}, {%0,%1,%2,%3};"
        : "+f"(c[0]), "+f"(c[1]), "+f"(c[2]), "+f"(c[3])
        : "r"(a[0]), "r"(a[1]), "r"(a[2]), "r"(a[3]), "r"(b[0]), "r"(b[1]));
}
__device__ __forceinline__ void cp16(uint32_t dst, const void* src) {
    asm volatile("cp.async.cg.shared.global [%0], [%1], 16;" :: "r"(dst), "l"(src));
}
#define CP_COMMIT() asm volatile("cp.async.commit_group;" ::: "memory")
#define CP_WAIT2()  asm volatile("cp.async.wait_group 2;" ::: "memory")

// ---------------------------------------------------------------------------
// fp16-input / fp32-accum GEMM via mma.sync m16n8k16:
//   D[m][n] = sum_k A[m][k] * B[n][k]   (A,B __half, k-contiguous)
// CTA tile 128x256, BK=64 halfs, 256 threads, warp tile 64x64 (2x4 warps).
// 4-stage cp.async(16B) pipeline; stage (48KB) = A 16KB + B 32KB;
//   16B chunk c of row r at r*128 + ((c^(r&7))<<4).
// OUT: 0 = fp32 C; 1 = fp16 C; 2 = attention-P epilogue:
//   e = (n<=m) ? exp(val*SCALE) : 0, stored fp16 to Ch[m][n], plus
//   per-s partials Z stored to Zp[m0/128][z*NT + n]  (tile skip n0>=m0+128).
// CKLIM: kend = min(K, m0+128).  BATCHN: n globally batched (b = n>>11).
// BIASN: bias[n].  BIASM: bias[m].
// ---------------------------------------------------------------------------
template<bool BIASN, bool BIASM, bool CKLIM, int OUT, bool BATCHN>
__global__ __launch_bounds__(256, 1)
void gemm_h(const __half* __restrict__ Ag, const __half* __restrict__ Bg,
            const float* __restrict__ bias, float* __restrict__ Cf,
            __half* __restrict__ Ch, float* __restrict__ Zp,
            int lda, int ldb, int ldc, int Ktot,
            size_t sA, size_t sB, size_t sC)
{
    extern __shared__ char smem[];
    const int m0 = blockIdx.y * 128;
    const int n0 = blockIdx.x * 256;
    if (OUT == 2 && n0 >= m0 + 128) return;   // causal: no s<=t in tile

    const __half* A = Ag + (size_t)blockIdx.z * sA;
    const __half* B = Bg + (size_t)blockIdx.z * sB;

    const int tid = threadIdx.x;
    const int lane = tid & 31;
    const int wid = tid >> 5;
    const int warp_m = (wid & 1) * 64;
    const int warp_n = (wid >> 1) * 64;
    const int g  = lane >> 2;    // 0..7
    const int tg = lane & 3;     // 0..3
    const uint32_t smem_u = smem_u32(smem);

    uint32_t col0[4], col1[4];
#pragma unroll
    for (int j = 0; j < 4; j++) {
        col0[j] = (((uint32_t)((2 * j)     ^ g)) << 4) + (uint32_t)tg * 4;
        col1[j] = (((uint32_t)((2 * j + 1) ^ g)) << 4) + (uint32_t)tg * 4;
    }
    uint32_t aoff[4], boff[8];
#pragma unroll
    for (int mt = 0; mt < 4; mt++)
        aoff[mt] = (uint32_t)(warp_m + mt * 16 + g) * 128;
#pragma unroll
    for (int nt = 0; nt < 8; nt++)
        boff[nt] = 16384u + (uint32_t)(warp_n + nt * 8 + g) * 128;

    const int lc = tid & 7;
    const int lr = tid >> 3;

    float acc[4][8][4];
#pragma unroll
    for (int mt = 0; mt < 4; mt++)
#pragma unroll
        for (int nt = 0; nt < 8; nt++)
#pragma unroll
            for (int r = 0; r < 4; r++) acc[mt][nt][r] = 0.f;

    const int kend = CKLIM ? min(Ktot, m0 + 128) : Ktot;
    const int nch = kend >> 6;   // BK = 64 halfs; >= 2 always here

    auto load_stage = [&](int slot, int chunk) {
        const uint32_t sbase = smem_u + (uint32_t)slot * 49152u;
        const int k0 = (chunk << 6) + lc * 8;
#pragma unroll
        for (int i = 0; i < 4; i++) {   // A: 128 rows
            const int r = lr + i * 32;
            const uint32_t off = (uint32_t)r * 128 + ((uint32_t)(lc ^ (r & 7)) << 4);
            cp16(sbase + off, A + (size_t)(m0 + r) * lda + k0);
        }
#pragma unroll
        for (int i = 0; i < 8; i++) {   // B: 256 rows
            const int r = lr + i * 32;
            const uint32_t off = (uint32_t)r * 128 + ((uint32_t)(lc ^ (r & 7)) << 4);
            cp16(sbase + 16384u + off, B + (size_t)(n0 + r) * ldb + k0);
        }
    };

#pragma unroll
    for (int s = 0; s < 3; s++) {
        if (s < nch) load_stage(s, s);
        CP_COMMIT();
    }

    for (int c = 0; c < nch; c++) {
        CP_WAIT2();
        __syncthreads();
        if (c + 3 < nch) load_stage((c + 3) & 3, c + 3);
        CP_COMMIT();

        const char* stage = smem + (size_t)(c & 3) * 49152;
#pragma unroll
        for (int ks = 0; ks < 4; ks++) {
            const uint32_t c0 = col0[ks], c1 = col1[ks];
            uint32_t a[4][4], b[8][2];
#pragma unroll
            for (int mt = 0; mt < 4; mt++) {
                a[mt][0] = *(const uint32_t*)(stage + aoff[mt] + c0);
                a[mt][1] = *(const uint32_t*)(stage + aoff[mt] + 8 * 128 + c0);
                a[mt][2] = *(const uint32_t*)(stage + aoff[mt] + c1);
                a[mt][3] = *(const uint32_t*)(stage + aoff[mt] + 8 * 128 + c1);
            }
#pragma unroll
            for (int nt = 0; nt < 8; nt++) {
                b[nt][0] = *(const uint32_t*)(stage + boff[nt] + c0);
                b[nt][1] = *(const uint32_t*)(stage + boff[nt] + c1);
            }
#pragma unroll
            for (int mt = 0; mt < 4; mt++)
#pragma unroll
                for (int nt = 0; nt < 8; nt++)
                    mma_f16(acc[mt][nt], a[mt], b[nt]);
        }
    }

    // ---- epilogue ----
    int nbase;
    size_t cofs;
    if (BATCHN) {
        cofs = (size_t)(n0 >> 11) * sC;
        nbase = n0 & 2047;
    } else {
        cofs = (size_t)blockIdx.z * sC;
        nbase = n0;
    }

    if (OUT == 2) {
        float zacc0[8], zacc1[8];
#pragma unroll
        for (int nt = 0; nt < 8; nt++) { zacc0[nt] = 0.f; zacc1[nt] = 0.f; }
#pragma unroll
        for (int mt = 0; mt < 4; mt++) {
            const int m = m0 + warp_m + mt * 16 + g;   // t
#pragma unroll
            for (int nt = 0; nt < 8; nt++) {
                const int n = n0 + warp_n + nt * 8 + tg * 2;   // s
                const float e00 = (n     <= m)     ? __expf(acc[mt][nt][0] * SCALE) : 0.f;
                const float e01 = (n + 1 <= m)     ? __expf(acc[mt][nt][1] * SCALE) : 0.f;
                const float e10 = (n     <= m + 8) ? __expf(acc[mt][nt][2] * SCALE) : 0.f;
                const float e11 = (n + 1 <= m + 8) ? __expf(acc[mt][nt][3] * SCALE) : 0.f;
                zacc0[nt] += e00 + e10;
                zacc1[nt] += e01 + e11;
                __half* crow = Ch + cofs + (size_t)m * ldc + n;
                *(__half2*)crow = __floats2half2_rn(e00, e01);
                *(__half2*)(crow + (size_t)8 * ldc) = __floats2half2_rn(e10, e11);
            }
        }
        __syncthreads();                       // stage smem now reusable
        float* zp = (float*)smem;              // [2][256]
#pragma unroll
        for (int nt = 0; nt < 8; nt++) {
            float s0 = zacc0[nt], s1 = zacc1[nt];
#pragma unroll
            for (int mk = 16; mk >= 4; mk >>= 1) {
                s0 += __shfl_xor_sync(0xffffffffu, s0, mk);
                s1 += __shfl_xor_sync(0xffffffffu, s1, mk);
            }
            if (lane < 4) {
                const int sl = warp_n + nt * 8 + tg * 2;
                zp[(wid & 1) * 256 + sl]     = s0;
                zp[(wid & 1) * 256 + sl + 1] = s1;
            }
        }
        __syncthreads();
        if (tid < 256)
            Zp[(size_t)(m0 >> 7) * (NB * NT) + (size_t)blockIdx.z * NT + n0 + tid]
                = zp[tid] + zp[256 + tid];
        return;
    }

#pragma unroll
    for (int mt = 0; mt < 4; mt++) {
        const int m = m0 + warp_m + mt * 16 + g;
#pragma unroll
        for (int nt = 0; nt < 8; nt++) {
            const int n = nbase + warp_n + nt * 8 + tg * 2;
            float v00 = acc[mt][nt][0], v01 = acc[mt][nt][1];
            float v10 = acc[mt][nt][2], v11 = acc[mt][nt][3];
            if (BIASN) {
                const float b0 = bias[n0 - nbase + n], b1 = bias[n0 - nbase + n + 1];
                v00 += b0; v01 += b1;
                v10 += b0; v11 += b1;
            }
            if (BIASM) {
                const float bm0 = bias[m], bm1 = bias[m + 8];
                v00 += bm0; v01 += bm0;
                v10 += bm1; v11 += bm1;
            }
            if (OUT == 1) {
                __half* crow = Ch + cofs + (size_t)m * ldc + n;
                *(__half2*)crow = __floats2half2_rn(v00, v01);
                *(__half2*)(crow + (size_t)8 * ldc) = __floats2half2_rn(v10, v11);
            } else {
                float* crow = Cf + cofs + (size_t)m * ldc + n;
                *(float2*)crow = make_float2(v00, v01);
                *(float2*)(crow + (size_t)8 * ldc) = make_float2(v10, v11);
            }
        }
    }
}

// ---------------------------------------------------------------------------
// x -> fp16 copy, fused with out[..., 0:512] = x
// ---------------------------------------------------------------------------
__global__ void cvt_x(const float4* __restrict__ in, __half2* __restrict__ xh2,
                      float4* __restrict__ out4, int n4)
{
    const int i = blockIdx.x * blockDim.x + threadIdx.x;
    if (i >= n4) return;
    const float4 v = in[i];
    xh2[2 * i + 0] = __floats2half2_rn(v.x, v.y);
    xh2[2 * i + 1] = __floats2half2_rn(v.z, v.w);
    const size_t row = (size_t)i >> 7;
    const size_t col = (size_t)i & 127;
    out4[row * 256 + col] = v;
}

// 512x512 transpose + fp16: WT[n][k] = W[k][n]
__global__ void trans512cv(const float* __restrict__ W, __half* __restrict__ WT)
{
    __shared__ float tile[32][33];
    const int tx = threadIdx.x & 31, ty = threadIdx.x >> 5;
    const int c0 = blockIdx.x * 32, r0 = blockIdx.y * 32;
#pragma unroll
    for (int r = 0; r < 4; r++)
        tile[ty + r * 8][tx] = W[(size_t)(r0 + ty + r * 8) * NC + c0 + tx];
    __syncthreads();
#pragma unroll
    for (int r = 0; r < 4; r++)
        WT[(size_t)(c0 + ty + r * 8) * NC + r0 + tx] = __float2half_rn(tile[tx][ty + r * 8]);
}

// Zinv[b][s] = 1 / sum_j zpart[j][b][s]
__global__ void zinv_k(const float* __restrict__ zp, float* __restrict__ zinv)
{
    const int i = blockIdx.x * 256 + threadIdx.x;
    float s = 0.f;
#pragma unroll
    for (int j = 0; j < 16; j++) s += zp[(size_t)j * (NB * NT) + i];
    zinv[i] = 1.f / s;
}

// vT[b][c][s] *= zinv[b][s]  (in place, fp16)
__global__ void vt_scale(__half2* __restrict__ vt, const float* __restrict__ zinv)
{
    const int i = blockIdx.x * blockDim.x + threadIdx.x;
    const int total = NB * NC * NT / 2;
    if (i >= total) return;
    const int s2 = (i & (NT / 2 - 1)) * 2;
    const int b = i / (NC * NT / 2);
    const float i0 = zinv[b * NT + s2];
    const float i1 = zinv[b * NT + s2 + 1];
    const float2 f = __half22float2(vt[i]);
    vt[i] = __floats2half2_rn(f.x * i0, f.y * i1);
}

// ---------------------------------------------------------------------------
extern "C" void kernel_launch(void* const* d_in, const int* in_sizes, int n_in,
                              void* d_out, int out_size)
{
    const float* x  = (const float*)d_in[0];
    const float* Wq = (const float*)d_in[1];
    const float* bq = (const float*)d_in[2];
    const float* Wk = (const float*)d_in[3];
    const float* bk = (const float*)d_in[4];
    const float* Wv = (const float*)d_in[5];
    const float* bv = (const float*)d_in[6];
    float* out = (float*)d_out;

    __half *xr, *wT, *q, *k, *vT, *p;
    float *zpart, *zinv;
    cudaGetSymbolAddress((void**)&xr,    g_xr);
    cudaGetSymbolAddress((void**)&wT,    g_wT);
    cudaGetSymbolAddress((void**)&q,     g_q);
    cudaGetSymbolAddress((void**)&k,     g_k);
    cudaGetSymbolAddress((void**)&vT,    g_vT);
    cudaGetSymbolAddress((void**)&p,     g_p);
    cudaGetSymbolAddress((void**)&zpart, g_zpart);
    cudaGetSymbolAddress((void**)&zinv,  g_zinv);

    const int SMEM = 4 * 49152;   // 196608
    cudaFuncSetAttribute(gemm_h<true,  false, false, 1, false>, cudaFuncAttributeMaxDynamicSharedMemorySize, SMEM);
    cudaFuncSetAttribute(gemm_h<false, true,  false, 1, true >, cudaFuncAttributeMaxDynamicSharedMemorySize, SMEM);
    cudaFuncSetAttribute(gemm_h<false, false, false, 2, false>, cudaFuncAttributeMaxDynamicSharedMemorySize, SMEM);
    cudaFuncSetAttribute(gemm_h<false, false, true,  0, false>, cudaFuncAttributeMaxDynamicSharedMemorySize, SMEM);

    const size_t strBT  = (size_t)NT * NC;
    const size_t strLG  = (size_t)NT * NT;
    const size_t strOUT = (size_t)NT * (2 * NC);

    // 0) operand prep + zero Z partials
    cvt_x<<<(NB * NT * NC / 4 + 255) / 256, 256>>>(
        (const float4*)x, (__half2*)xr, (float4*)out, NB * NT * NC / 4);
    trans512cv<<<dim3(16, 16), 256>>>(Wq, wT + 0 * NC * NC);
    trans512cv<<<dim3(16, 16), 256>>>(Wk, wT + 1 * NC * NC);
    trans512cv<<<dim3(16, 16), 256>>>(Wv, wT + 2 * NC * NC);
    cudaMemsetAsync(zpart, 0, (size_t)16 * NB * NT * sizeof(float), 0);

    // 1) Q,K projections -> fp16
    {
        dim3 grid(NC / 256, (NB * NT) / 128, 1);
        gemm_h<true, false, false, 1, false><<<grid, 256, SMEM>>>(
            xr, wT + 0 * NC * NC, bq, nullptr, q, nullptr, NC, NC, NC, NC, 0, 0, 0);
        gemm_h<true, false, false, 1, false><<<grid, 256, SMEM>>>(
            xr, wT + 1 * NC * NC, bk, nullptr, k, nullptr, NC, NC, NC, NC, 0, 0, 0);
    }
    // 1v) V projection, transposed: vT[b][c][t] = sum_k WvT[c][k] x[b,t,k] + bv[c]
    {
        dim3 grid((NB * NT) / 256, NC / 128, 1);
        gemm_h<false, true, false, 1, true><<<grid, 256, SMEM>>>(
            wT + 2 * NC * NC, xr, bv, nullptr, vT, nullptr, NC, NC, NT, NC, 0, 0, (size_t)NC * NT);
    }

    // 2) P[b][t][s] = (s<=t) ? exp(q.k * SCALE) : 0   (fp16) + Z partials
    {
        dim3 grid(NT / 256, NT / 128, NB);   // n = s, m = t
        gemm_h<false, false, false, 2, false><<<grid, 256, SMEM>>>(
            q, k, nullptr, nullptr, p, zpart, NC, NC, NT, NC, strBT, strBT, strLG);
    }

    // 3) Z reduce -> zinv; fold normalization into vT
    zinv_k<<<NB * NT / 256, 256>>>(zpart, zinv);
    vt_scale<<<(NB * NC * NT / 2 + 255) / 256, 256>>>((__half2*)vT, zinv);

    // 4) read[b][t][v] = sum_s P[b,t,s] * vT'[b,v,s]  -> out[..., 512:1024]
    {
        dim3 grid(NC / 256, NT / 128, NB);
        gemm_h<false, false, true, 0, false><<<grid, 256, SMEM>>>(
            p, vT, nullptr, out + NC, nullptr, nullptr, NT, NT, 2 * NC, NT,
            strLG, (size_t)NC * NT, strOUT);
    }
}

// round 13
// speedup vs baseline: 4.2119x; 1.0392x over previous
#include <cuda_runtime.h>
#include <cuda_fp16.h>
#include <cstdint>
#include <math.h>

#define NB 8
#define NT 2048
#define NC 512
#define SCALE 0.04419417382415922f   // 1/sqrt(512)

// ---------------- scratch (__device__ globals; allocation-free rule) --------
__device__ __align__(256) __half g_xr [NB * NT * NC];          // x, fp16
__device__ __align__(256) __half g_wT [3 * NC * NC];           // WqT|WkT|WvT fp16
__device__ __align__(256) __half g_qk [(size_t)NB * NT * 1024];// [b·t][q 512 | k 512]
__device__ __align__(256) __half g_vT [NB * NT * NC];          // fp16 [b][c][t]
__device__ __align__(256) __half g_p  [(size_t)NB * NT * NT];  // P=exp [b][t][s] fp16
__device__ __align__(256) float  g_bqk[1024];                  // bq|bk concat
__device__ __align__(256) float  g_zpart[16 * NB * NT];        // per-t-tile Z partials
__device__ __align__(256) float  g_zinv [NB * NT];             // 1/Z[s]

// ---------------- helpers ---------------------------------------------------
__device__ __forceinline__ uint32_t smem_u32(const void* p) {
    uint32_t a;
    asm("{ .reg .u64 t; cvta.to.shared.u64 t, %1; cvt.u32.u64 %0, t; }" : "=r"(a) : "l"(p));
    return a;
}
__device__ __forceinline__ void mma_f16(float* c, const uint32_t* a, const uint32_t* b) {
    asm volatile(
        "mma.sync.aligned.m16n8k16.row.col.f32.f16.f16.f32 "
        "{%0,%1,%2,%3}, {%4,%5,%6,%7}, {%8,%9}, {%0,%1,%2,%3};"
        : "+f"(c[0]), "+f"(c[1]), "+f"(c[2]), "+f"(c[3])
        : "r"(a[0]), "r"(a[1]), "r"(a[2]), "r"(a[3]), "r"(b[0]), "r"(b[1]));
}
__device__ __forceinline__ void ldsm4(uint32_t* r, uint32_t addr) {
    asm volatile("ldmatrix.sync.aligned.m8n8.x4.shared.b16 {%0,%1,%2,%3}, [%4];"
                 : "=r"(r[0]), "=r"(r[1]), "=r"(r[2]), "=r"(r[3]) : "r"(addr));
}
__device__ __forceinline__ void cp16(uint32_t dst, const void* src) {
    asm volatile("cp.async.cg.shared.global [%0], [%1], 16;" :: "r"(dst), "l"(src));
}
#define CP_COMMIT() asm volatile("cp.async.commit_group;" ::: "memory")
#define CP_WAIT2()  asm volatile("cp.async.wait_group 2;" ::: "memory")

// ---------------------------------------------------------------------------
// fp16-input / fp32-accum GEMM via mma.sync m16n8k16 + ldmatrix fragments:
//   D[m][n] = sum_k A[m][k] * B[n][k]   (A,B __half, k-contiguous)
// CTA tile 128x256, BK=64 halfs, 256 threads, warp tile 64x64 (2x4 warps).
// 4-stage cp.async(16B) pipeline; stage (48KB) = A 16KB + B 32KB;
//   16B chunk c of row r at r*128 + ((c^(r&7))<<4).
// OUT: 0 = fp32 C; 1 = fp16 C; 2 = attention-P epilogue (exp+mask+Z partials).
// CKLIM: kend = min(K, m0+128) with REVERSED y-order (long tiles first).
// BATCHN: n globally batched (b = n>>11).  BIASN: bias[n].  BIASM: bias[m].
// ---------------------------------------------------------------------------
template<bool BIASN, bool BIASM, bool CKLIM, int OUT, bool BATCHN>
__global__ __launch_bounds__(256, 1)
void gemm_h(const __half* __restrict__ Ag, const __half* __restrict__ Bg,
            const float* __restrict__ bias, float* __restrict__ Cf,
            __half* __restrict__ Ch, float* __restrict__ Zp,
            int lda, int ldb, int ldc, int Ktot,
            size_t sA, size_t sB, size_t sC)
{
    extern __shared__ char smem[];
    const int m0 = CKLIM ? (int)(gridDim.y - 1 - blockIdx.y) * 128
                         : (int)blockIdx.y * 128;
    const int n0 = blockIdx.x * 256;
    if (OUT == 2 && n0 >= m0 + 128) return;   // causal: no s<=t in tile

    const __half* A = Ag + (size_t)blockIdx.z * sA;
    const __half* B = Bg + (size_t)blockIdx.z * sB;

    const int tid = threadIdx.x;
    const int lane = tid & 31;
    const int wid = tid >> 5;
    const int warp_m = (wid & 1) * 64;
    const int warp_n = (wid >> 1) * 64;
    const int g  = lane >> 2;    // 0..7
    const int tg = lane & 3;     // 0..3
    const uint32_t smem_u = smem_u32(smem);

    // ---- ldmatrix per-lane addresses ----
    const int low = lane & 7;
    // A: lanes 0-7 -> (rows +0..7, chunk 2ks); 8-15 -> (+8, 2ks); 16-23 -> (+0, 2ks+1); 24-31 -> (+8, 2ks+1)
    const int a_hi  = lane >> 4;          // chunk +0/+1
    const int a_mid = (lane >> 3) & 1;    // row +0/+8
    uint32_t arow[4];
#pragma unroll
    for (int mt = 0; mt < 4; mt++)
        arow[mt] = (uint32_t)(warp_m + mt * 16 + a_mid * 8 + low) * 128;
    uint32_t cswzA[4];
#pragma unroll
    for (int ks = 0; ks < 4; ks++)
        cswzA[ks] = (uint32_t)(((2 * ks + a_hi) ^ low) << 4);
    // B: lanes 0-7 -> (nt rows, c0); 8-15 -> (nt, c1); 16-23 -> (nt+1, c0); 24-31 -> (nt+1, c1)
    const int b_sel = lane >> 3;          // 0..3
    const int b_hi  = b_sel & 1;          // chunk +0/+1
    const int b_mid = b_sel >> 1;         // row +0/+8
    uint32_t brow[4];
#pragma unroll
    for (int np = 0; np < 4; np++)
        brow[np] = 16384u + (uint32_t)(warp_n + np * 16 + b_mid * 8 + low) * 128;
    uint32_t cswzB[4];
#pragma unroll
    for (int ks = 0; ks < 4; ks++)
        cswzB[ks] = (uint32_t)(((2 * ks + b_hi) ^ low) << 4);

    const int lc = tid & 7;
    const int lr = tid >> 3;

    float acc[4][8][4];
#pragma unroll
    for (int mt = 0; mt < 4; mt++)
#pragma unroll
        for (int nt = 0; nt < 8; nt++)
#pragma unroll
            for (int r = 0; r < 4; r++) acc[mt][nt][r] = 0.f;

    const int kend = CKLIM ? min(Ktot, m0 + 128) : Ktot;
    const int nch = kend >> 6;   // BK = 64 halfs; >= 2 always here

    auto load_stage = [&](int slot, int chunk) {
        const uint32_t sbase = smem_u + (uint32_t)slot * 49152u;
        const int k0 = (chunk << 6) + lc * 8;
#pragma unroll
        for (int i = 0; i < 4; i++) {   // A: 128 rows
            const int r = lr + i * 32;
            const uint32_t off = (uint32_t)r * 128 + ((uint32_t)(lc ^ (r & 7)) << 4);
            cp16(sbase + off, A + (size_t)(m0 + r) * lda + k0);
        }
#pragma unroll
        for (int i = 0; i < 8; i++) {   // B: 256 rows
            const int r = lr + i * 32;
            const uint32_t off = (uint32_t)r * 128 + ((uint32_t)(lc ^ (r & 7)) << 4);
            cp16(sbase + 16384u + off, B + (size_t)(n0 + r) * ldb + k0);
        }
    };

#pragma unroll
    for (int s = 0; s < 3; s++) {
        if (s < nch) load_stage(s, s);
        CP_COMMIT();
    }

    for (int c = 0; c < nch; c++) {
        CP_WAIT2();
        __syncthreads();
        if (c + 3 < nch) load_stage((c + 3) & 3, c + 3);
        CP_COMMIT();

        const uint32_t su = smem_u + (uint32_t)(c & 3) * 49152u;
#pragma unroll
        for (int ks = 0; ks < 4; ks++) {
            uint32_t a[4][4], b[8][2];
#pragma unroll
            for (int mt = 0; mt < 4; mt++)
                ldsm4(a[mt], su + arow[mt] + cswzA[ks]);
#pragma unroll
            for (int np = 0; np < 4; np++) {
                uint32_t t4[4];
                ldsm4(t4, su + brow[np] + cswzB[ks]);
                b[2 * np][0]     = t4[0];
                b[2 * np][1]     = t4[1];
                b[2 * np + 1][0] = t4[2];
                b[2 * np + 1][1] = t4[3];
            }
#pragma unroll
            for (int mt = 0; mt < 4; mt++)
#pragma unroll
                for (int nt = 0; nt < 8; nt++)
                    mma_f16(acc[mt][nt], a[mt], b[nt]);
        }
    }

    // ---- epilogue ----
    int nbase;
    size_t cofs;
    if (BATCHN) {
        cofs = (size_t)(n0 >> 11) * sC;
        nbase = n0 & 2047;
    } else {
        cofs = (size_t)blockIdx.z * sC;
        nbase = n0;
    }

    if (OUT == 2) {
        float zacc0[8], zacc1[8];
#pragma unroll
        for (int nt = 0; nt < 8; nt++) { zacc0[nt] = 0.f; zacc1[nt] = 0.f; }
#pragma unroll
        for (int mt = 0; mt < 4; mt++) {
            const int m = m0 + warp_m + mt * 16 + g;   // t
#pragma unroll
            for (int nt = 0; nt < 8; nt++) {
                const int n = n0 + warp_n + nt * 8 + tg * 2;   // s
                const float e00 = (n     <= m)     ? __expf(acc[mt][nt][0] * SCALE) : 0.f;
                const float e01 = (n + 1 <= m)     ? __expf(acc[mt][nt][1] * SCALE) : 0.f;
                const float e10 = (n     <= m + 8) ? __expf(acc[mt][nt][2] * SCALE) : 0.f;
                const float e11 = (n + 1 <= m + 8) ? __expf(acc[mt][nt][3] * SCALE) : 0.f;
                zacc0[nt] += e00 + e10;
                zacc1[nt] += e01 + e11;
                __half* crow = Ch + cofs + (size_t)m * ldc + n;
                *(__half2*)crow = __floats2half2_rn(e00, e01);
                *(__half2*)(crow + (size_t)8 * ldc) = __floats2half2_rn(e10, e11);
            }
        }
        __syncthreads();                       // stage smem now reusable
        float* zp = (float*)smem;              // [2][256]
#pragma unroll
        for (int nt = 0; nt < 8; nt++) {
            float s0 = zacc0[nt], s1 = zacc1[nt];
#pragma unroll
            for (int mk = 16; mk >= 4; mk >>= 1) {
                s0 += __shfl_xor_sync(0xffffffffu, s0, mk);
                s1 += __shfl_xor_sync(0xffffffffu, s1, mk);
            }
            if (lane < 4) {
                const int sl = warp_n + nt * 8 + tg * 2;
                zp[(wid & 1) * 256 + sl]     = s0;
                zp[(wid & 1) * 256 + sl + 1] = s1;
            }
        }
        __syncthreads();
        if (tid < 256)
            Zp[(size_t)(m0 >> 7) * (NB * NT) + (size_t)blockIdx.z * NT + n0 + tid]
                = zp[tid] + zp[256 + tid];
        return;
    }

#pragma unroll
    for (int mt = 0; mt < 4; mt++) {
        const int m = m0 + warp_m + mt * 16 + g;
#pragma unroll
        for (int nt = 0; nt < 8; nt++) {
            const int n = nbase + warp_n + nt * 8 + tg * 2;
            float v00 = acc[mt][nt][0], v01 = acc[mt][nt][1];
            float v10 = acc[mt][nt][2], v11 = acc[mt][nt][3];
            if (BIASN) {
                const float b0 = bias[n0 - nbase + n], b1 = bias[n0 - nbase + n + 1];
                v00 += b0; v01 += b1;
                v10 += b0; v11 += b1;
            }
            if (BIASM) {
                const float bm0 = bias[m], bm1 = bias[m + 8];
                v00 += bm0; v01 += bm0;
                v10 += bm1; v11 += bm1;
            }
            if (OUT == 1) {
                __half* crow = Ch + cofs + (size_t)m * ldc + n;
                *(__half2*)crow = __floats2half2_rn(v00, v01);
                *(__half2*)(crow + (size_t)8 * ldc) = __floats2half2_rn(v10, v11);
            } else {
                float* crow = Cf + cofs + (size_t)m * ldc + n;
                *(float2*)crow = make_float2(v00, v01);
                *(float2*)(crow + (size_t)8 * ldc) = make_float2(v10, v11);
            }
        }
    }
}

// ---------------------------------------------------------------------------
// x -> fp16 copy, fused with out[..., 0:512] = x
// ---------------------------------------------------------------------------
__global__ void cvt_x(const float4* __restrict__ in, __half2* __restrict__ xh2,
                      float4* __restrict__ out4, int n4)
{
    const int i = blockIdx.x * blockDim.x + threadIdx.x;
    if (i >= n4) return;
    const float4 v = in[i];
    xh2[2 * i + 0] = __floats2half2_rn(v.x, v.y);
    xh2[2 * i + 1] = __floats2half2_rn(v.z, v.w);
    const size_t row = (size_t)i >> 7;
    const size_t col = (size_t)i & 127;
    out4[row * 256 + col] = v;
}

// Merged weight transposes (z=0..2) + bias concat (z=3).
__global__ void prep_w(const float* __restrict__ W0, const float* __restrict__ W1,
                       const float* __restrict__ W2, const float* __restrict__ bq,
                       const float* __restrict__ bk, __half* __restrict__ WT,
                       float* __restrict__ bqk)
{
    if (blockIdx.z == 3) {
        if (blockIdx.y == 0 && blockIdx.x < 4) {
            const int i = blockIdx.x * 256 + threadIdx.x;
            bqk[i] = (i < 512) ? bq[i] : bk[i - 512];
        }
        return;
    }
    const float* W = (blockIdx.z == 0) ? W0 : (blockIdx.z == 1) ? W1 : W2;
    __half* WTo = WT + (size_t)blockIdx.z * NC * NC;
    __shared__ float tile[32][33];
    const int tx = threadIdx.x & 31, ty = threadIdx.x >> 5;
    const int c0 = blockIdx.x * 32, r0 = blockIdx.y * 32;
#pragma unroll
    for (int r = 0; r < 4; r++)
        tile[ty + r * 8][tx] = W[(size_t)(r0 + ty + r * 8) * NC + c0 + tx];
    __syncthreads();
#pragma unroll
    for (int r = 0; r < 4; r++)
        WTo[(size_t)(c0 + ty + r * 8) * NC + r0 + tx] = __float2half_rn(tile[tx][ty + r * 8]);
}

// Zinv[b][s] = 1 / sum_j zpart[j][b][s]
__global__ void zinv_k(const float* __restrict__ zp, float* __restrict__ zinv)
{
    const int i = blockIdx.x * 256 + threadIdx.x;
    float s = 0.f;
#pragma unroll
    for (int j = 0; j < 16; j++) s += zp[(size_t)j * (NB * NT) + i];
    zinv[i] = 1.f / s;
}

// vT[b][c][s] *= zinv[b][s]  (in place, fp16)
__global__ void vt_scale(__half2* __restrict__ vt, const float* __restrict__ zinv)
{
    const int i = blockIdx.x * blockDim.x + threadIdx.x;
    const int total = NB * NC * NT / 2;
    if (i >= total) return;
    const int s2 = (i & (NT / 2 - 1)) * 2;
    const int b = i / (NC * NT / 2);
    const float i0 = zinv[b * NT + s2];
    const float i1 = zinv[b * NT + s2 + 1];
    const float2 f = __half22float2(vt[i]);
    vt[i] = __floats2half2_rn(f.x * i0, f.y * i1);
}

// ---------------------------------------------------------------------------
extern "C" void kernel_launch(void* const* d_in, const int* in_sizes, int n_in,
                              void* d_out, int out_size)
{
    const float* x  = (const float*)d_in[0];
    const float* Wq = (const float*)d_in[1];
    const float* bq = (const float*)d_in[2];
    const float* Wk = (const float*)d_in[3];
    const float* bk = (const float*)d_in[4];
    const float* Wv = (const float*)d_in[5];
    const float* bv = (const float*)d_in[6];
    float* out = (float*)d_out;

    __half *xr, *wT, *qk, *vT, *p;
    float *bqk, *zpart, *zinv;
    cudaGetSymbolAddress((void**)&xr,    g_xr);
    cudaGetSymbolAddress((void**)&wT,    g_wT);
    cudaGetSymbolAddress((void**)&qk,    g_qk);
    cudaGetSymbolAddress((void**)&vT,    g_vT);
    cudaGetSymbolAddress((void**)&p,     g_p);
    cudaGetSymbolAddress((void**)&bqk,   g_bqk);
    cudaGetSymbolAddress((void**)&zpart, g_zpart);
    cudaGetSymbolAddress((void**)&zinv,  g_zinv);

    const int SMEM = 4 * 49152;   // 196608
    cudaFuncSetAttribute(gemm_h<true,  false, false, 1, false>, cudaFuncAttributeMaxDynamicSharedMemorySize, SMEM);
    cudaFuncSetAttribute(gemm_h<false, true,  false, 1, true >, cudaFuncAttributeMaxDynamicSharedMemorySize, SMEM);
    cudaFuncSetAttribute(gemm_h<false, false, false, 2, false>, cudaFuncAttributeMaxDynamicSharedMemorySize, SMEM);
    cudaFuncSetAttribute(gemm_h<false, false, true,  0, false>, cudaFuncAttributeMaxDynamicSharedMemorySize, SMEM);

    const size_t strQK  = (size_t)NT * 1024;
    const size_t strLG  = (size_t)NT * NT;
    const size_t strOUT = (size_t)NT * (2 * NC);

    // 0) operand prep + zero Z partials
    cvt_x<<<(NB * NT * NC / 4 + 255) / 256, 256>>>(
        (const float4*)x, (__half2*)xr, (float4*)out, NB * NT * NC / 4);
    prep_w<<<dim3(16, 16, 4), 256>>>(Wq, Wk, Wv, bq, bk, wT, bqk);
    cudaMemsetAsync(zpart, 0, (size_t)16 * NB * NT * sizeof(float), 0);

    // 1) merged Q|K projection: qk[b·t][0:512]=q, [512:1024]=k  (N=1024)
    {
        dim3 grid(1024 / 256, (NB * NT) / 128, 1);
        gemm_h<true, false, false, 1, false><<<grid, 256, SMEM>>>(
            xr, wT, bqk, nullptr, qk, nullptr, NC, NC, 1024, NC, 0, 0, 0);
    }
    // 1v) V projection, transposed: vT[b][c][t] = sum_k WvT[c][k] x[b,t,k] + bv[c]
    {
        dim3 grid((NB * NT) / 256, NC / 128, 1);
        gemm_h<false, true, false, 1, true><<<grid, 256, SMEM>>>(
            wT + 2 * NC * NC, xr, bv, nullptr, vT, nullptr, NC, NC, NT, NC, 0, 0, (size_t)NC * NT);
    }

    // 2) P[b][t][s] = (s<=t) ? exp(q.k * SCALE) : 0  (fp16) + Z partials
    {
        dim3 grid(NT / 256, NT / 128, NB);   // m = t (A = q), n = s (B = k)
        gemm_h<false, false, false, 2, false><<<grid, 256, SMEM>>>(
            qk, qk + 512, nullptr, nullptr, p, zpart, 1024, 1024, NT, NC,
            strQK, strQK, strLG);
    }

    // 3) Z reduce -> zinv; fold normalization into vT
    zinv_k<<<NB * NT / 256, 256>>>(zpart, zinv);
    vt_scale<<<(NB * NC * NT / 2 + 255) / 256, 256>>>((__half2*)vT, zinv);

    // 4) read[b][t][v] = sum_s P[b,t,s] * vT'[b,v,s]  -> out[..., 512:1024]
    {
        dim3 grid(NC / 256, NT / 128, NB);
        gemm_h<false, false, true, 0, false><<<grid, 256, SMEM>>>(
            p, vT, nullptr, out + NC, nullptr, nullptr, NT, NT, 2 * NC, NT,
            strLG, (size_t)NC * NT, strOUT);
    }
}

// round 14
// speedup vs baseline: 4.9046x; 1.1645x over previous
#include <cuda_runtime.h>
#include <cuda_fp16.h>
#include <cstdint>
#include <math.h>

#define NB 8
#define NT 2048
#define NC 512
#define SCALE 0.04419417382415922f   // 1/sqrt(512)

// ---------------- scratch (__device__ globals; allocation-free rule) --------
__device__ __align__(256) __half g_xr [NB * NT * NC];          // x, fp16
__device__ __align__(256) __half g_wT [3 * NC * NC];           // WqT|WkT|WvT fp16
__device__ __align__(256) __half g_qk [(size_t)NB * NT * 1024];// [b·t][q 512 | k 512]
__device__ __align__(256) __half g_vT [NB * NT * NC];          // fp16 [b][c][t]
__device__ __align__(256) __half g_p  [(size_t)NB * NT * NT];  // P=exp [b][t][s] fp16
__device__ __align__(256) float  g_bqk[1024];                  // bq|bk concat
__device__ __align__(256) float  g_zpart[16 * NB * NT];        // per-t-tile Z partials
__device__ __align__(256) float  g_zinv [NB * NT];             // 1/Z[s]

// ---------------- helpers ---------------------------------------------------
__device__ __forceinline__ uint32_t smem_u32(const void* p) {
    uint32_t a;
    asm("{ .reg .u64 t; cvta.to.shared.u64 t, %1; cvt.u32.u64 %0, t; }" : "=r"(a) : "l"(p));
    return a;
}
__device__ __forceinline__ void mma_f16(float* c, const uint32_t* a, const uint32_t* b) {
    asm volatile(
        "mma.sync.aligned.m16n8k16.row.col.f32.f16.f16.f32 "
        "{%0,%1,%2,%3}, {%4,%5,%6,%7}, {%8,%9}, {%0,%1,%2,%3};"
        : "+f"(c[0]), "+f"(c[1]), "+f"(c[2]), "+f"(c[3])
        : "r"(a[0]), "r"(a[1]), "r"(a[2]), "r"(a[3]), "r"(b[0]), "r"(b[1]));
}
__device__ __forceinline__ void ldsm4(uint32_t* r, uint32_t addr) {
    asm volatile("ldmatrix.sync.aligned.m8n8.x4.shared.b16 {%0,%1,%2,%3}, [%4];"
                 : "=r"(r[0]), "=r"(r[1]), "=r"(r[2]), "=r"(r[3]) : "r"(addr));
}
__device__ __forceinline__ void cp16(uint32_t dst, const void* src) {
    asm volatile("cp.async.cg.shared.global [%0], [%1], 16;" :: "r"(dst), "l"(src));
}
#define CP_COMMIT() asm volatile("cp.async.commit_group;" ::: "memory")
#define CP_WAIT1()  asm volatile("cp.async.wait_group 1;" ::: "memory")

// ---------------------------------------------------------------------------
// fp16-input / fp32-accum GEMM via mma.sync m16n8k16 + ldmatrix fragments:
//   D[m][n] = sum_k A[m][k] * B[n][k]   (A,B __half, k-contiguous)
// CTA tile 128x128, BK=64 halfs, 128 threads, warp tile 64x64 (2x2 warps),
// 2 CTAs/SM.  3-stage cp.async(16B) pipeline; stage (32KB) = A 16KB + B 16KB;
//   16B chunk c of row r at r*128 + ((c^(r&7))<<4).
// Per iter: wait_group(1), sync, issue load c+2 (slot freed at iter c-1), commit.
// OUT: 0 = fp32 C; 1 = fp16 C; 2 = attention-P epilogue (exp+mask+Z partials).
// CKLIM: kend = min(K, m0+128), REVERSED y-order.  BATCHN: b = n>>11.
// BIASN: bias[n].  BIASM: bias[m].
// ---------------------------------------------------------------------------
template<bool BIASN, bool BIASM, bool CKLIM, int OUT, bool BATCHN>
__global__ __launch_bounds__(128, 2)
void gemm_h(const __half* __restrict__ Ag, const __half* __restrict__ Bg,
            const float* __restrict__ bias, float* __restrict__ Cf,
            __half* __restrict__ Ch, float* __restrict__ Zp,
            int lda, int ldb, int ldc, int Ktot,
            size_t sA, size_t sB, size_t sC)
{
    extern __shared__ char smem[];
    const int m0 = CKLIM ? (int)(gridDim.y - 1 - blockIdx.y) * 128
                         : (int)blockIdx.y * 128;
    const int n0 = blockIdx.x * 128;
    if (OUT == 2 && n0 >= m0 + 128) return;   // causal: no s<=t in tile

    const __half* A = Ag + (size_t)blockIdx.z * sA;
    const __half* B = Bg + (size_t)blockIdx.z * sB;

    const int tid = threadIdx.x;
    const int lane = tid & 31;
    const int wid = tid >> 5;              // 0..3
    const int warp_m = (wid & 1) * 64;
    const int warp_n = (wid >> 1) * 64;
    const int g  = lane >> 2;    // 0..7
    const int tg = lane & 3;     // 0..3
    const uint32_t smem_u = smem_u32(smem);

    // ---- ldmatrix per-lane addresses ----
    const int low = lane & 7;
    const int a_hi  = lane >> 4;          // chunk +0/+1
    const int a_mid = (lane >> 3) & 1;    // row +0/+8
    uint32_t arow[4];
#pragma unroll
    for (int mt = 0; mt < 4; mt++)
        arow[mt] = (uint32_t)(warp_m + mt * 16 + a_mid * 8 + low) * 128;
    uint32_t cswzA[4];
#pragma unroll
    for (int ks = 0; ks < 4; ks++)
        cswzA[ks] = (uint32_t)(((2 * ks + a_hi) ^ low) << 4);
    const int b_sel = lane >> 3;          // 0..3
    const int b_hi  = b_sel & 1;          // chunk +0/+1
    const int b_mid = b_sel >> 1;         // row +0/+8
    uint32_t brow[4];
#pragma unroll
    for (int np = 0; np < 4; np++)
        brow[np] = 16384u + (uint32_t)(warp_n + np * 16 + b_mid * 8 + low) * 128;
    uint32_t cswzB[4];
#pragma unroll
    for (int ks = 0; ks < 4; ks++)
        cswzB[ks] = (uint32_t)(((2 * ks + b_hi) ^ low) << 4);

    // loader: lc = 16B chunk 0..7 within row, lr = row base 0..15 (+16i)
    const int lc = tid & 7;
    const int lr = tid >> 3;

    float acc[4][8][4];
#pragma unroll
    for (int mt = 0; mt < 4; mt++)
#pragma unroll
        for (int nt = 0; nt < 8; nt++)
#pragma unroll
            for (int r = 0; r < 4; r++) acc[mt][nt][r] = 0.f;

    const int kend = CKLIM ? min(Ktot, m0 + 128) : Ktot;
    const int nch = kend >> 6;   // BK = 64 halfs; >= 2 always here

    auto load_stage = [&](int slot, int chunk) {
        const uint32_t sbase = smem_u + (uint32_t)slot * 32768u;
        const int k0 = (chunk << 6) + lc * 8;
#pragma unroll
        for (int i = 0; i < 8; i++) {   // A: 128 rows
            const int r = lr + i * 16;
            const uint32_t off = (uint32_t)r * 128 + ((uint32_t)(lc ^ (r & 7)) << 4);
            cp16(sbase + off, A + (size_t)(m0 + r) * lda + k0);
        }
#pragma unroll
        for (int i = 0; i < 8; i++) {   // B: 128 rows
            const int r = lr + i * 16;
            const uint32_t off = (uint32_t)r * 128 + ((uint32_t)(lc ^ (r & 7)) << 4);
            cp16(sbase + 16384u + off, B + (size_t)(n0 + r) * ldb + k0);
        }
    };

    // prologue: stages 0,1
#pragma unroll
    for (int s = 0; s < 2; s++) {
        if (s < nch) load_stage(s, s);
        CP_COMMIT();
    }

    for (int c = 0; c < nch; c++) {
        CP_WAIT1();          // commits = c+2 ; completed >= c+1  => chunk c ready
        __syncthreads();     // all warps done with chunk c-1 (slot c+2 target)
        if (c + 2 < nch) load_stage((c + 2) % 3, c + 2);
        CP_COMMIT();

        const uint32_t su = smem_u + (uint32_t)(c % 3) * 32768u;
#pragma unroll
        for (int ks = 0; ks < 4; ks++) {
            uint32_t a[4][4], b[8][2];
#pragma unroll
            for (int mt = 0; mt < 4; mt++)
                ldsm4(a[mt], su + arow[mt] + cswzA[ks]);
#pragma unroll
            for (int np = 0; np < 4; np++) {
                uint32_t t4[4];
                ldsm4(t4, su + brow[np] + cswzB[ks]);
                b[2 * np][0]     = t4[0];
                b[2 * np][1]     = t4[1];
                b[2 * np + 1][0] = t4[2];
                b[2 * np + 1][1] = t4[3];
            }
#pragma unroll
            for (int mt = 0; mt < 4; mt++)
#pragma unroll
                for (int nt = 0; nt < 8; nt++)
                    mma_f16(acc[mt][nt], a[mt], b[nt]);
        }
    }

    // ---- epilogue ----
    int nbase;
    size_t cofs;
    if (BATCHN) {
        cofs = (size_t)(n0 >> 11) * sC;
        nbase = n0 & 2047;
    } else {
        cofs = (size_t)blockIdx.z * sC;
        nbase = n0;
    }

    if (OUT == 2) {
        float zacc0[8], zacc1[8];
#pragma unroll
        for (int nt = 0; nt < 8; nt++) { zacc0[nt] = 0.f; zacc1[nt] = 0.f; }
#pragma unroll
        for (int mt = 0; mt < 4; mt++) {
            const int m = m0 + warp_m + mt * 16 + g;   // t
#pragma unroll
            for (int nt = 0; nt < 8; nt++) {
                const int n = n0 + warp_n + nt * 8 + tg * 2;   // s
                const float e00 = (n     <= m)     ? __expf(acc[mt][nt][0] * SCALE) : 0.f;
                const float e01 = (n + 1 <= m)     ? __expf(acc[mt][nt][1] * SCALE) : 0.f;
                const float e10 = (n     <= m + 8) ? __expf(acc[mt][nt][2] * SCALE) : 0.f;
                const float e11 = (n + 1 <= m + 8) ? __expf(acc[mt][nt][3] * SCALE) : 0.f;
                zacc0[nt] += e00 + e10;
                zacc1[nt] += e01 + e11;
                __half* crow = Ch + cofs + (size_t)m * ldc + n;
                *(__half2*)crow = __floats2half2_rn(e00, e01);
                *(__half2*)(crow + (size_t)8 * ldc) = __floats2half2_rn(e10, e11);
            }
        }
        __syncthreads();                       // stage smem now reusable
        float* zp = (float*)smem;              // [2][128]
#pragma unroll
        for (int nt = 0; nt < 8; nt++) {
            float s0 = zacc0[nt], s1 = zacc1[nt];
#pragma unroll
            for (int mk = 16; mk >= 4; mk >>= 1) {
                s0 += __shfl_xor_sync(0xffffffffu, s0, mk);
                s1 += __shfl_xor_sync(0xffffffffu, s1, mk);
            }
            if (lane < 4) {
                const int sl = warp_n + nt * 8 + tg * 2;
                zp[(wid & 1) * 128 + sl]     = s0;
                zp[(wid & 1) * 128 + sl + 1] = s1;
            }
        }
        __syncthreads();
        Zp[(size_t)(m0 >> 7) * (NB * NT) + (size_t)blockIdx.z * NT + n0 + tid]
            = zp[tid] + zp[128 + tid];
        return;
    }

#pragma unroll
    for (int mt = 0; mt < 4; mt++) {
        const int m = m0 + warp_m + mt * 16 + g;
#pragma unroll
        for (int nt = 0; nt < 8; nt++) {
            const int n = nbase + warp_n + nt * 8 + tg * 2;
            float v00 = acc[mt][nt][0], v01 = acc[mt][nt][1];
            float v10 = acc[mt][nt][2], v11 = acc[mt][nt][3];
            if (BIASN) {
                const float b0 = bias[n0 - nbase + n], b1 = bias[n0 - nbase + n + 1];
                v00 += b0; v01 += b1;
                v10 += b0; v11 += b1;
            }
            if (BIASM) {
                const float bm0 = bias[m], bm1 = bias[m + 8];
                v00 += bm0; v01 += bm0;
                v10 += bm1; v11 += bm1;
            }
            if (OUT == 1) {
                __half* crow = Ch + cofs + (size_t)m * ldc + n;
                *(__half2*)crow = __floats2half2_rn(v00, v01);
                *(__half2*)(crow + (size_t)8 * ldc) = __floats2half2_rn(v10, v11);
            } else {
                float* crow = Cf + cofs + (size_t)m * ldc + n;
                *(float2*)crow = make_float2(v00, v01);
                *(float2*)(crow + (size_t)8 * ldc) = make_float2(v10, v11);
            }
        }
    }
}

// ---------------------------------------------------------------------------
// x -> fp16 copy, fused with out[..., 0:512] = x
// ---------------------------------------------------------------------------
__global__ void cvt_x(const float4* __restrict__ in, __half2* __restrict__ xh2,
                      float4* __restrict__ out4, int n4)
{
    const int i = blockIdx.x * blockDim.x + threadIdx.x;
    if (i >= n4) return;
    const float4 v = in[i];
    xh2[2 * i + 0] = __floats2half2_rn(v.x, v.y);
    xh2[2 * i + 1] = __floats2half2_rn(v.z, v.w);
    const size_t row = (size_t)i >> 7;
    const size_t col = (size_t)i & 127;
    out4[row * 256 + col] = v;
}

// Merged weight transposes (z=0..2) + bias concat (z=3).
__global__ void prep_w(const float* __restrict__ W0, const float* __restrict__ W1,
                       const float* __restrict__ W2, const float* __restrict__ bq,
                       const float* __restrict__ bk, __half* __restrict__ WT,
                       float* __restrict__ bqk)
{
    if (blockIdx.z == 3) {
        if (blockIdx.y == 0 && blockIdx.x < 4) {
            const int i = blockIdx.x * 256 + threadIdx.x;
            bqk[i] = (i < 512) ? bq[i] : bk[i - 512];
        }
        return;
    }
    const float* W = (blockIdx.z == 0) ? W0 : (blockIdx.z == 1) ? W1 : W2;
    __half* WTo = WT + (size_t)blockIdx.z * NC * NC;
    __shared__ float tile[32][33];
    const int tx = threadIdx.x & 31, ty = threadIdx.x >> 5;
    const int c0 = blockIdx.x * 32, r0 = blockIdx.y * 32;
#pragma unroll
    for (int r = 0; r < 4; r++)
        tile[ty + r * 8][tx] = W[(size_t)(r0 + ty + r * 8) * NC + c0 + tx];
    __syncthreads();
#pragma unroll
    for (int r = 0; r < 4; r++)
        WTo[(size_t)(c0 + ty + r * 8) * NC + r0 + tx] = __float2half_rn(tile[tx][ty + r * 8]);
}

// Zinv[b][s] = 1 / sum_j zpart[j][b][s]
__global__ void zinv_k(const float* __restrict__ zp, float* __restrict__ zinv)
{
    const int i = blockIdx.x * 256 + threadIdx.x;
    float s = 0.f;
#pragma unroll
    for (int j = 0; j < 16; j++) s += zp[(size_t)j * (NB * NT) + i];
    zinv[i] = 1.f / s;
}

// vT[b][c][s] *= zinv[b][s]  (in place, fp16)
__global__ void vt_scale(__half2* __restrict__ vt, const float* __restrict__ zinv)
{
    const int i = blockIdx.x * blockDim.x + threadIdx.x;
    const int total = NB * NC * NT / 2;
    if (i >= total) return;
    const int s2 = (i & (NT / 2 - 1)) * 2;
    const int b = i / (NC * NT / 2);
    const float i0 = zinv[b * NT + s2];
    const float i1 = zinv[b * NT + s2 + 1];
    const float2 f = __half22float2(vt[i]);
    vt[i] = __floats2half2_rn(f.x * i0, f.y * i1);
}

// ---------------------------------------------------------------------------
extern "C" void kernel_launch(void* const* d_in, const int* in_sizes, int n_in,
                              void* d_out, int out_size)
{
    const float* x  = (const float*)d_in[0];
    const float* Wq = (const float*)d_in[1];
    const float* bq = (const float*)d_in[2];
    const float* Wk = (const float*)d_in[3];
    const float* bk = (const float*)d_in[4];
    const float* Wv = (const float*)d_in[5];
    const float* bv = (const float*)d_in[6];
    float* out = (float*)d_out;

    __half *xr, *wT, *qk, *vT, *p;
    float *bqk, *zpart, *zinv;
    cudaGetSymbolAddress((void**)&xr,    g_xr);
    cudaGetSymbolAddress((void**)&wT,    g_wT);
    cudaGetSymbolAddress((void**)&qk,    g_qk);
    cudaGetSymbolAddress((void**)&vT,    g_vT);
    cudaGetSymbolAddress((void**)&p,     g_p);
    cudaGetSymbolAddress((void**)&bqk,   g_bqk);
    cudaGetSymbolAddress((void**)&zpart, g_zpart);
    cudaGetSymbolAddress((void**)&zinv,  g_zinv);

    const int SMEM = 3 * 32768;   // 98304 per CTA; 2 CTAs/SM
    cudaFuncSetAttribute(gemm_h<true,  false, false, 1, false>, cudaFuncAttributeMaxDynamicSharedMemorySize, SMEM);
    cudaFuncSetAttribute(gemm_h<false, true,  false, 1, true >, cudaFuncAttributeMaxDynamicSharedMemorySize, SMEM);
    cudaFuncSetAttribute(gemm_h<false, false, false, 2, false>, cudaFuncAttributeMaxDynamicSharedMemorySize, SMEM);
    cudaFuncSetAttribute(gemm_h<false, false, true,  0, false>, cudaFuncAttributeMaxDynamicSharedMemorySize, SMEM);

    const size_t strQK  = (size_t)NT * 1024;
    const size_t strLG  = (size_t)NT * NT;
    const size_t strOUT = (size_t)NT * (2 * NC);

    // 0) operand prep + zero Z partials
    cvt_x<<<(NB * NT * NC / 4 + 255) / 256, 256>>>(
        (const float4*)x, (__half2*)xr, (float4*)out, NB * NT * NC / 4);
    prep_w<<<dim3(16, 16, 4), 256>>>(Wq, Wk, Wv, bq, bk, wT, bqk);
    cudaMemsetAsync(zpart, 0, (size_t)16 * NB * NT * sizeof(float), 0);

    // 1) merged Q|K projection: qk[b·t][0:512]=q, [512:1024]=k  (N=1024)
    {
        dim3 grid(1024 / 128, (NB * NT) / 128, 1);
        gemm_h<true, false, false, 1, false><<<grid, 128, SMEM>>>(
            xr, wT, bqk, nullptr, qk, nullptr, NC, NC, 1024, NC, 0, 0, 0);
    }
    // 1v) V projection, transposed: vT[b][c][t] = sum_k WvT[c][k] x[b,t,k] + bv[c]
    {
        dim3 grid((NB * NT) / 128, NC / 128, 1);
        gemm_h<false, true, false, 1, true><<<grid, 128, SMEM>>>(
            wT + 2 * NC * NC, xr, bv, nullptr, vT, nullptr, NC, NC, NT, NC, 0, 0, (size_t)NC * NT);
    }

    // 2) P[b][t][s] = (s<=t) ? exp(q.k * SCALE) : 0  (fp16) + Z partials
    {
        dim3 grid(NT / 128, NT / 128, NB);   // m = t (A = q), n = s (B = k)
        gemm_h<false, false, false, 2, false><<<grid, 128, SMEM>>>(
            qk, qk + 512, nullptr, nullptr, p, zpart, 1024, 1024, NT, NC,
            strQK, strQK, strLG);
    }

    // 3) Z reduce -> zinv; fold normalization into vT
    zinv_k<<<NB * NT / 256, 256>>>(zpart, zinv);
    vt_scale<<<(NB * NC * NT / 2 + 255) / 256, 256>>>((__half2*)vT, zinv);

    // 4) read[b][t][v] = sum_s P[b,t,s] * vT'[b,v,s]  -> out[..., 512:1024]
    {
        dim3 grid(NC / 128, NT / 128, NB);
        gemm_h<false, false, true, 0, false><<<grid, 128, SMEM>>>(
            p, vT, nullptr, out + NC, nullptr, nullptr, NT, NT, 2 * NC, NT,
            strLG, (size_t)NC * NT, strOUT);
    }
}

// round 15
// speedup vs baseline: 5.1495x; 1.0499x over previous
#include <cuda_runtime.h>
#include <cuda_fp16.h>
#include <cstdint>
#include <math.h>

#define NB 8
#define NT 2048
#define NC 512
#define SCALE 0.04419417382415922f   // 1/sqrt(512)

// ---------------- scratch (__device__ globals; allocation-free rule) --------
__device__ __align__(256) __half g_xr [NB * NT * NC];          // x, fp16
__device__ __align__(256) __half g_wT [3 * NC * NC];           // WqT|WkT|WvT fp16
__device__ __align__(256) __half g_qk [(size_t)NB * NT * 1024];// [b·t][q 512 | k 512]
__device__ __align__(256) __half g_vT [NB * NT * NC];          // fp16 [b][c][t], pre-normalized
__device__ __align__(256) __half g_p  [(size_t)NB * NT * NT];  // P=exp [b][t][s] fp16
__device__ __align__(256) float  g_bqk[1024];                  // bq|bk concat
__device__ __align__(256) float  g_zpart[16 * NB * NT];        // per-t-tile Z partials
__device__ __align__(256) float  g_zinv [NB * NT];             // 1/Z[s]

// ---------------- helpers ---------------------------------------------------
__device__ __forceinline__ uint32_t smem_u32(const void* p) {
    uint32_t a;
    asm("{ .reg .u64 t; cvta.to.shared.u64 t, %1; cvt.u32.u64 %0, t; }" : "=r"(a) : "l"(p));
    return a;
}
__device__ __forceinline__ void mma_f16(float* c, const uint32_t* a, const uint32_t* b) {
    asm volatile(
        "mma.sync.aligned.m16n8k16.row.col.f32.f16.f16.f32 "
        "{%0,%1,%2,%3}, {%4,%5,%6,%7}, {%8,%9}, {%0,%1,%2,%3};"
        : "+f"(c[0]), "+f"(c[1]), "+f"(c[2]), "+f"(c[3])
        : "r"(a[0]), "r"(a[1]), "r"(a[2]), "r"(a[3]), "r"(b[0]), "r"(b[1]));
}
__device__ __forceinline__ void ldsm4(uint32_t* r, uint32_t addr) {
    asm volatile("ldmatrix.sync.aligned.m8n8.x4.shared.b16 {%0,%1,%2,%3}, [%4];"
                 : "=r"(r[0]), "=r"(r[1]), "=r"(r[2]), "=r"(r[3]) : "r"(addr));
}
__device__ __forceinline__ void cp16(uint32_t dst, const void* src) {
    asm volatile("cp.async.cg.shared.global [%0], [%1], 16;" :: "r"(dst), "l"(src));
}
#define CP_COMMIT() asm volatile("cp.async.commit_group;" ::: "memory")
#define CP_WAIT1()  asm volatile("cp.async.wait_group 1;" ::: "memory")

// ---------------------------------------------------------------------------
// fp16-input / fp32-accum GEMM via mma.sync m16n8k16 + ldmatrix fragments:
//   D[m][n] = sum_k A[m][k] * B[n][k]   (A,B __half, k-contiguous)
// CTA tile 128x128, BK=64 halfs, 128 threads, warp tile 64x64 (2x2 warps),
// 2 CTAs/SM.  3-stage cp.async(16B) pipeline; stage (32KB) = A 16KB + B 16KB;
//   16B chunk c of row r at r*128 + ((c^(r&7))<<4).
// Per iter: wait_group(1), sync, issue load c+2 (slot freed at iter c-1), commit.
// OUT: 0 = fp32 C; 1 = fp16 C; 2 = attention-P epilogue (exp+mask+Z partials).
// SCALEN: multiply output by Zs[global n] before store (fp16 path).
// CKLIM: kend = min(K, m0+128), REVERSED y-order.  BATCHN: b = n>>11.
// BIASN: bias[n].  BIASM: bias[m].
// ---------------------------------------------------------------------------
template<bool BIASN, bool BIASM, bool CKLIM, int OUT, bool BATCHN, bool SCALEN>
__global__ __launch_bounds__(128, 2)
void gemm_h(const __half* __restrict__ Ag, const __half* __restrict__ Bg,
            const float* __restrict__ bias, const float* __restrict__ Zs,
            float* __restrict__ Cf, __half* __restrict__ Ch, float* __restrict__ Zp,
            int lda, int ldb, int ldc, int Ktot,
            size_t sA, size_t sB, size_t sC)
{
    extern __shared__ char smem[];
    const int m0 = CKLIM ? (int)(gridDim.y - 1 - blockIdx.y) * 128
                         : (int)blockIdx.y * 128;
    const int n0 = blockIdx.x * 128;
    if (OUT == 2 && n0 >= m0 + 128) return;   // causal: no s<=t in tile

    const __half* A = Ag + (size_t)blockIdx.z * sA;
    const __half* B = Bg + (size_t)blockIdx.z * sB;

    const int tid = threadIdx.x;
    const int lane = tid & 31;
    const int wid = tid >> 5;              // 0..3
    const int warp_m = (wid & 1) * 64;
    const int warp_n = (wid >> 1) * 64;
    const int g  = lane >> 2;    // 0..7
    const int tg = lane & 3;     // 0..3
    const uint32_t smem_u = smem_u32(smem);

    // ---- ldmatrix per-lane addresses ----
    const int low = lane & 7;
    const int a_hi  = lane >> 4;          // chunk +0/+1
    const int a_mid = (lane >> 3) & 1;    // row +0/+8
    uint32_t arow[4];
#pragma unroll
    for (int mt = 0; mt < 4; mt++)
        arow[mt] = (uint32_t)(warp_m + mt * 16 + a_mid * 8 + low) * 128;
    uint32_t cswzA[4];
#pragma unroll
    for (int ks = 0; ks < 4; ks++)
        cswzA[ks] = (uint32_t)(((2 * ks + a_hi) ^ low) << 4);
    const int b_sel = lane >> 3;          // 0..3
    const int b_hi  = b_sel & 1;          // chunk +0/+1
    const int b_mid = b_sel >> 1;         // row +0/+8
    uint32_t brow[4];
#pragma unroll
    for (int np = 0; np < 4; np++)
        brow[np] = 16384u + (uint32_t)(warp_n + np * 16 + b_mid * 8 + low) * 128;
    uint32_t cswzB[4];
#pragma unroll
    for (int ks = 0; ks < 4; ks++)
        cswzB[ks] = (uint32_t)(((2 * ks + b_hi) ^ low) << 4);

    // loader: lc = 16B chunk 0..7 within row, lr = row base 0..15 (+16i)
    const int lc = tid & 7;
    const int lr = tid >> 3;

    float acc[4][8][4];
#pragma unroll
    for (int mt = 0; mt < 4; mt++)
#pragma unroll
        for (int nt = 0; nt < 8; nt++)
#pragma unroll
            for (int r = 0; r < 4; r++) acc[mt][nt][r] = 0.f;

    const int kend = CKLIM ? min(Ktot, m0 + 128) : Ktot;
    const int nch = kend >> 6;   // BK = 64 halfs; >= 2 always here

    auto load_stage = [&](int slot, int chunk) {
        const uint32_t sbase = smem_u + (uint32_t)slot * 32768u;
        const int k0 = (chunk << 6) + lc * 8;
#pragma unroll
        for (int i = 0; i < 8; i++) {   // A: 128 rows
            const int r = lr + i * 16;
            const uint32_t off = (uint32_t)r * 128 + ((uint32_t)(lc ^ (r & 7)) << 4);
            cp16(sbase + off, A + (size_t)(m0 + r) * lda + k0);
        }
#pragma unroll
        for (int i = 0; i < 8; i++) {   // B: 128 rows
            const int r = lr + i * 16;
            const uint32_t off = (uint32_t)r * 128 + ((uint32_t)(lc ^ (r & 7)) << 4);
            cp16(sbase + 16384u + off, B + (size_t)(n0 + r) * ldb + k0);
        }
    };

    // prologue: stages 0,1
#pragma unroll
    for (int s = 0; s < 2; s++) {
        if (s < nch) load_stage(s, s);
        CP_COMMIT();
    }

    for (int c = 0; c < nch; c++) {
        CP_WAIT1();          // commits = c+2 ; completed >= c+1  => chunk c ready
        __syncthreads();     // all warps done with chunk c-1 (slot c+2 target)
        if (c + 2 < nch) load_stage((c + 2) % 3, c + 2);
        CP_COMMIT();

        const uint32_t su = smem_u + (uint32_t)(c % 3) * 32768u;
#pragma unroll
        for (int ks = 0; ks < 4; ks++) {
            uint32_t a[4][4], b[8][2];
#pragma unroll
            for (int mt = 0; mt < 4; mt++)
                ldsm4(a[mt], su + arow[mt] + cswzA[ks]);
#pragma unroll
            for (int np = 0; np < 4; np++) {
                uint32_t t4[4];
                ldsm4(t4, su + brow[np] + cswzB[ks]);
                b[2 * np][0]     = t4[0];
                b[2 * np][1]     = t4[1];
                b[2 * np + 1][0] = t4[2];
                b[2 * np + 1][1] = t4[3];
            }
#pragma unroll
            for (int mt = 0; mt < 4; mt++)
#pragma unroll
                for (int nt = 0; nt < 8; nt++)
                    mma_f16(acc[mt][nt], a[mt], b[nt]);
        }
    }

    // ---- epilogue ----
    int nbase;
    size_t cofs;
    if (BATCHN) {
        cofs = (size_t)(n0 >> 11) * sC;
        nbase = n0 & 2047;
    } else {
        cofs = (size_t)blockIdx.z * sC;
        nbase = n0;
    }

    if (OUT == 2) {
        float zacc0[8], zacc1[8];
#pragma unroll
        for (int nt = 0; nt < 8; nt++) { zacc0[nt] = 0.f; zacc1[nt] = 0.f; }
#pragma unroll
        for (int mt = 0; mt < 4; mt++) {
            const int m = m0 + warp_m + mt * 16 + g;   // t
#pragma unroll
            for (int nt = 0; nt < 8; nt++) {
                const int n = n0 + warp_n + nt * 8 + tg * 2;   // s
                const float e00 = (n     <= m)     ? __expf(acc[mt][nt][0] * SCALE) : 0.f;
                const float e01 = (n + 1 <= m)     ? __expf(acc[mt][nt][1] * SCALE) : 0.f;
                const float e10 = (n     <= m + 8) ? __expf(acc[mt][nt][2] * SCALE) : 0.f;
                const float e11 = (n + 1 <= m + 8) ? __expf(acc[mt][nt][3] * SCALE) : 0.f;
                zacc0[nt] += e00 + e10;
                zacc1[nt] += e01 + e11;
                __half* crow = Ch + cofs + (size_t)m * ldc + n;
                *(__half2*)crow = __floats2half2_rn(e00, e01);
                *(__half2*)(crow + (size_t)8 * ldc) = __floats2half2_rn(e10, e11);
            }
        }
        __syncthreads();                       // stage smem now reusable
        float* zp = (float*)smem;              // [2][128]
#pragma unroll
        for (int nt = 0; nt < 8; nt++) {
            float s0 = zacc0[nt], s1 = zacc1[nt];
#pragma unroll
            for (int mk = 16; mk >= 4; mk >>= 1) {
                s0 += __shfl_xor_sync(0xffffffffu, s0, mk);
                s1 += __shfl_xor_sync(0xffffffffu, s1, mk);
            }
            if (lane < 4) {
                const int sl = warp_n + nt * 8 + tg * 2;
                zp[(wid & 1) * 128 + sl]     = s0;
                zp[(wid & 1) * 128 + sl + 1] = s1;
            }
        }
        __syncthreads();
        Zp[(size_t)(m0 >> 7) * (NB * NT) + (size_t)blockIdx.z * NT + n0 + tid]
            = zp[tid] + zp[128 + tid];
        return;
    }

#pragma unroll
    for (int mt = 0; mt < 4; mt++) {
        const int m = m0 + warp_m + mt * 16 + g;
#pragma unroll
        for (int nt = 0; nt < 8; nt++) {
            const int n = nbase + warp_n + nt * 8 + tg * 2;
            float v00 = acc[mt][nt][0], v01 = acc[mt][nt][1];
            float v10 = acc[mt][nt][2], v11 = acc[mt][nt][3];
            if (BIASN) {
                const float b0 = bias[n0 - nbase + n], b1 = bias[n0 - nbase + n + 1];
                v00 += b0; v01 += b1;
                v10 += b0; v11 += b1;
            }
            if (BIASM) {
                const float bm0 = bias[m], bm1 = bias[m + 8];
                v00 += bm0; v01 += bm0;
                v10 += bm1; v11 += bm1;
            }
            if (SCALEN) {
                const int gn = n0 - nbase + n;   // global token index
                const float z0 = Zs[gn], z1 = Zs[gn + 1];
                v00 *= z0; v01 *= z1;
                v10 *= z0; v11 *= z1;
            }
            if (OUT == 1) {
                __half* crow = Ch + cofs + (size_t)m * ldc + n;
                *(__half2*)crow = __floats2half2_rn(v00, v01);
                *(__half2*)(crow + (size_t)8 * ldc) = __floats2half2_rn(v10, v11);
            } else {
                float* crow = Cf + cofs + (size_t)m * ldc + n;
                *(float2*)crow = make_float2(v00, v01);
                *(float2*)(crow + (size_t)8 * ldc) = make_float2(v10, v11);
            }
        }
    }
}

// ---------------------------------------------------------------------------
// x -> fp16 copy, fused with out[..., 0:512] = x
// ---------------------------------------------------------------------------
__global__ void cvt_x(const float4* __restrict__ in, __half2* __restrict__ xh2,
                      float4* __restrict__ out4, int n4)
{
    const int i = blockIdx.x * blockDim.x + threadIdx.x;
    if (i >= n4) return;
    const float4 v = in[i];
    xh2[2 * i + 0] = __floats2half2_rn(v.x, v.y);
    xh2[2 * i + 1] = __floats2half2_rn(v.z, v.w);
    const size_t row = (size_t)i >> 7;
    const size_t col = (size_t)i & 127;
    out4[row * 256 + col] = v;
}

// Merged weight transposes (z=0..2) + bias concat (z=3).
__global__ void prep_w(const float* __restrict__ W0, const float* __restrict__ W1,
                       const float* __restrict__ W2, const float* __restrict__ bq,
                       const float* __restrict__ bk, __half* __restrict__ WT,
                       float* __restrict__ bqk)
{
    if (blockIdx.z == 3) {
        if (blockIdx.y == 0 && blockIdx.x < 4) {
            const int i = blockIdx.x * 256 + threadIdx.x;
            bqk[i] = (i < 512) ? bq[i] : bk[i - 512];
        }
        return;
    }
    const float* W = (blockIdx.z == 0) ? W0 : (blockIdx.z == 1) ? W1 : W2;
    __half* WTo = WT + (size_t)blockIdx.z * NC * NC;
    __shared__ float tile[32][33];
    const int tx = threadIdx.x & 31, ty = threadIdx.x >> 5;
    const int c0 = blockIdx.x * 32, r0 = blockIdx.y * 32;
#pragma unroll
    for (int r = 0; r < 4; r++)
        tile[ty + r * 8][tx] = W[(size_t)(r0 + ty + r * 8) * NC + c0 + tx];
    __syncthreads();
#pragma unroll
    for (int r = 0; r < 4; r++)
        WTo[(size_t)(c0 + ty + r * 8) * NC + r0 + tx] = __float2half_rn(tile[tx][ty + r * 8]);
}

// Zinv[b][s] = 1 / sum_j zpart[j][b][s]
__global__ void zinv_k(const float* __restrict__ zp, float* __restrict__ zinv)
{
    const int i = blockIdx.x * 256 + threadIdx.x;
    float s = 0.f;
#pragma unroll
    for (int j = 0; j < 16; j++) s += zp[(size_t)j * (NB * NT) + i];
    zinv[i] = 1.f / s;
}

// ---------------------------------------------------------------------------
extern "C" void kernel_launch(void* const* d_in, const int* in_sizes, int n_in,
                              void* d_out, int out_size)
{
    const float* x  = (const float*)d_in[0];
    const float* Wq = (const float*)d_in[1];
    const float* bq = (const float*)d_in[2];
    const float* Wk = (const float*)d_in[3];
    const float* bk = (const float*)d_in[4];
    const float* Wv = (const float*)d_in[5];
    const float* bv = (const float*)d_in[6];
    float* out = (float*)d_out;

    __half *xr, *wT, *qk, *vT, *p;
    float *bqk, *zpart, *zinv;
    cudaGetSymbolAddress((void**)&xr,    g_xr);
    cudaGetSymbolAddress((void**)&wT,    g_wT);
    cudaGetSymbolAddress((void**)&qk,    g_qk);
    cudaGetSymbolAddress((void**)&vT,    g_vT);
    cudaGetSymbolAddress((void**)&p,     g_p);
    cudaGetSymbolAddress((void**)&bqk,   g_bqk);
    cudaGetSymbolAddress((void**)&zpart, g_zpart);
    cudaGetSymbolAddress((void**)&zinv,  g_zinv);

    const int SMEM = 3 * 32768;   // 98304 per CTA; 2 CTAs/SM
    cudaFuncSetAttribute(gemm_h<true,  false, false, 1, false, false>, cudaFuncAttributeMaxDynamicSharedMemorySize, SMEM);
    cudaFuncSetAttribute(gemm_h<false, true,  false, 1, true,  true >, cudaFuncAttributeMaxDynamicSharedMemorySize, SMEM);
    cudaFuncSetAttribute(gemm_h<false, false, false, 2, false, false>, cudaFuncAttributeMaxDynamicSharedMemorySize, SMEM);
    cudaFuncSetAttribute(gemm_h<false, false, true,  0, false, false>, cudaFuncAttributeMaxDynamicSharedMemorySize, SMEM);

    const size_t strQK  = (size_t)NT * 1024;
    const size_t strLG  = (size_t)NT * NT;
    const size_t strOUT = (size_t)NT * (2 * NC);

    // 0) operand prep + zero Z partials
    cvt_x<<<(NB * NT * NC / 4 + 255) / 256, 256>>>(
        (const float4*)x, (__half2*)xr, (float4*)out, NB * NT * NC / 4);
    prep_w<<<dim3(16, 16, 4), 256>>>(Wq, Wk, Wv, bq, bk, wT, bqk);
    cudaMemsetAsync(zpart, 0, (size_t)16 * NB * NT * sizeof(float), 0);

    // 1) merged Q|K projection: qk[b·t][0:512]=q, [512:1024]=k  (N=1024)
    {
        dim3 grid(1024 / 128, (NB * NT) / 128, 1);
        gemm_h<true, false, false, 1, false, false><<<grid, 128, SMEM>>>(
            xr, wT, bqk, nullptr, nullptr, qk, nullptr, NC, NC, 1024, NC, 0, 0, 0);
    }

    // 2) P[b][t][s] = (s<=t) ? exp(q.k * SCALE) : 0  (fp16) + Z partials
    {
        dim3 grid(NT / 128, NT / 128, NB);   // m = t (A = q), n = s (B = k)
        gemm_h<false, false, false, 2, false, false><<<grid, 128, SMEM>>>(
            qk, qk + 512, nullptr, nullptr, nullptr, p, zpart, 1024, 1024, NT, NC,
            strQK, strQK, strLG);
    }

    // 3) Z reduce -> zinv
    zinv_k<<<NB * NT / 256, 256>>>(zpart, zinv);

    // 4) V projection, transposed + pre-normalized:
    //    vT[b][c][t] = (sum_k WvT[c][k] x[b,t,k] + bv[c]) * zinv[b][t]
    {
        dim3 grid((NB * NT) / 128, NC / 128, 1);   // n = global token, m = channel
        gemm_h<false, true, false, 1, true, true><<<grid, 128, SMEM>>>(
            wT + 2 * NC * NC, xr, bv, zinv, nullptr, vT, nullptr,
            NC, NC, NT, NC, 0, 0, (size_t)NC * NT);
    }

    // 5) read[b][t][v] = sum_s P[b,t,s] * vT[b,v,s]  -> out[..., 512:1024]
    {
        dim3 grid(NC / 128, NT / 128, NB);
        gemm_h<false, false, true, 0, false, false><<<grid, 128, SMEM>>>(
            p, vT, nullptr, nullptr, out + NC, nullptr, nullptr, NT, NT, 2 * NC, NT,
            strLG, (size_t)NC * NT, strOUT);
    }
}